// round 9
// baseline (speedup 1.0000x reference)
#include <cuda_runtime.h>
#include <math_constants.h>

#define BB 4
#define HH 512
#define WW 512
#define HW (HH*WW)
#define NKPT 512
#define CAP 65536
#define NFEAT 128

#define TILE 64
#define HALO 15
#define LDIM (TILE + 2*HALO)     // 94
#define G 3                      // guard ring
#define RROWS (LDIM + 2*G)       // 100
#define SPITCH 100
#define BUF (RROWS*SPITCH)       // 10000
#define WPR 5                    // bit-words per row (slots 0,4 = zero guards)
#define NMS_SMEM (BUF*4*2 + RROWS*WPR*4*3)   // 86000 B
#define NMS_THREADS 512
#define NMS_NW (NMS_THREADS/32)

#define SURVCAP 3072

// Output layout (float32, reference tuple order)
#define OFF_SCORE 0
#define OFF_KPTS  (BB*HW)
#define OFF_FEAS  (OFF_KPTS + BB*NKPT*4)
#define OFF_PIX   (OFF_FEAS + BB*NFEAT*NKPT)

// Scratch
__device__ unsigned long long g_cand[BB*CAP];
__device__ unsigned char g_cmask[BB*HW];
__device__ int g_count[BB];
__device__ int g_sel[BB*NKPT];

// ---------------------------------------------------------------------------
// Fused NMS. One block per 64x64 tile. Float pools in smem; mask/dilation as
// bitboards. Emit (score2d + candidates) fused into the final pass.
// ---------------------------------------------------------------------------
__global__ __launch_bounds__(NMS_THREADS, 2)
void k_nms(const float* __restrict__ bev,
           const float* __restrict__ raw,
           float* __restrict__ out) {
    extern __shared__ unsigned char smraw[];
    float* sbuf = (float*)smraw;
    float* tbuf = sbuf + BUF;
    unsigned int* mkw = (unsigned int*)(tbuf + BUF);  // max_mask bits
    unsigned int* hbw = mkw + RROWS*WPR;              // h-dilated bits
    unsigned int* spw = hbw + RROWS*WPR;              // supp (7x7 dil) bits
    float* sc = sbuf + G*SPITCH + G;
    float* tp = tbuf + G*SPITCH + G;

    const int tid  = threadIdx.x;
    const int wid  = tid >> 5;
    const int lane = tid & 31;
    const int b    = blockIdx.z;
    const int gx0  = blockIdx.x * TILE - HALO;
    const int gy0  = blockIdx.y * TILE - HALO;
    const float* g2 = bev + (b*7 + 2)*HW;
    const float* rw = raw + b*HW;

    // bit arrays + tp guard rows init
    for (int i = tid; i < RROWS*WPR; i += NMS_THREADS) {
        mkw[i] = 0; hbw[i] = 0; spw[i] = 0;
    }
    for (int i = tid; i < 6*SPITCH; i += NMS_THREADS) {
        int r = (i < 3*SPITCH) ? i : (RROWS-3)*SPITCH + (i - 3*SPITCH);
        tbuf[r] = -CUDART_INF_F;
    }

    // fused init+load over the FULL ring: gated score or -inf
    for (int r = wid; r < RROWS; r += NMS_NW) {
        int gy = gy0 + (r - G);
        const float* rwr = rw + gy*WW;
        const float* g2r = g2 + gy*WW;
        bool rowin = (unsigned)gy < HH;
        for (int col = lane; col < SPITCH; col += 32) {
            int gx = gx0 + (col - G);
            float v = -CUDART_INF_F;
            if (rowin && (unsigned)gx < WW)
                v = rwr[gx] * (g2r[gx] > 0.f ? 1.f : 0.f);
            sbuf[r*SPITCH + col] = v;
        }
    }
    __syncthreads();

    // P1: h 7-max sc -> tp
    for (int ly = wid; ly < LDIM; ly += NMS_NW) {
        const float* row = sc + ly*SPITCH;
        for (int lx = lane; lx < LDIM; lx += 32) {
            float m = row[lx-3];
            #pragma unroll
            for (int k = -2; k <= 3; ++k) m = fmaxf(m, row[lx+k]);
            tp[ly*SPITCH + lx] = m;
        }
    }
    __syncthreads();
    // P2: v 7-max of tp; mk bit = (max == sc) & in-image
    for (int ly = wid; ly < LDIM; ly += NMS_NW) {
        for (int g = 0; g < 3; ++g) {
            int lx = g*32 + lane;
            bool pred = false;
            if (lx < LDIM) {
                const float* col = tp + ly*SPITCH + lx;
                float m = col[-3*SPITCH];
                #pragma unroll
                for (int k = -2; k <= 3; ++k) m = fmaxf(m, col[k*SPITCH]);
                float sv = sc[ly*SPITCH + lx];
                pred = (m == sv && sv >= 0.f);
            }
            unsigned bal = __ballot_sync(0xffffffffu, pred);
            if (lane == 0) mkw[(ly+G)*WPR + 1 + g] = bal;
        }
    }
    __syncthreads();

    for (int it = 0; it < 2; ++it) {
        // P3: h-dilate mk bits
        for (int t = tid; t < 300; t += NMS_THREADS) {
            int row = t / 3, w = t % 3 + 1;
            const unsigned int* mr = mkw + row*WPR;
            unsigned a = mr[w-1], c = mr[w], d = mr[w+1];
            unsigned res = c;
            res |= __funnelshift_l(a, c, 1) | __funnelshift_r(c, d, 1);
            res |= __funnelshift_l(a, c, 2) | __funnelshift_r(c, d, 2);
            res |= __funnelshift_l(a, c, 3) | __funnelshift_r(c, d, 3);
            hbw[row*WPR + w] = res;
        }
        __syncthreads();
        // P4: v-dilate
        for (int t = tid; t < 282; t += NMS_THREADS) {
            int row = t / 3 + 3, w = t % 3 + 1;
            unsigned r = 0;
            #pragma unroll
            for (int k = -3; k <= 3; ++k) r |= hbw[(row+k)*WPR + w];
            spw[row*WPR + w] = r;
        }
        __syncthreads();
        // P5: h 7-max of (supbit ? 0 : sc) -> tp
        for (int ly = wid; ly < LDIM; ly += NMS_NW) {
            const float* srow = sc + ly*SPITCH;
            const unsigned int* sr = spw + (ly+G)*WPR + 1;
            for (int lx = lane; lx < LDIM; lx += 32) {
                float m = -CUDART_INF_F;
                #pragma unroll
                for (int k = -3; k <= 3; ++k) {
                    int B = lx + k;
                    unsigned wv = sr[B >> 5];
                    float v = ((wv >> (B & 31)) & 1u) ? 0.f : srow[lx+k];
                    m = fmaxf(m, v);
                }
                tp[ly*SPITCH + lx] = m;
            }
        }
        __syncthreads();
        // P6: v 7-max of tp; cond = (!sup & sv>=0 & m==sv)
        for (int ly = wid; ly < LDIM; ly += NMS_NW) {
            const unsigned int* sr = spw + (ly+G)*WPR + 1;
            unsigned int* mr = mkw + (ly+G)*WPR + 1;
            for (int g = 0; g < 3; ++g) {
                int lx = g*32 + lane;
                bool cond = false;
                float sv = 0.f;
                unsigned oldw = mr[g];
                if (lx < LDIM) {
                    const float* col = tp + ly*SPITCH + lx;
                    float m = col[-3*SPITCH];
                    #pragma unroll
                    for (int k = -2; k <= 3; ++k) m = fmaxf(m, col[k*SPITCH]);
                    sv = sc[ly*SPITCH + lx];
                    unsigned supb = (sr[g] >> lane) & 1u;
                    cond = (!supb && sv >= 0.f && m == sv);
                }
                if (it == 0) {
                    unsigned bal = __ballot_sync(0xffffffffu, cond);
                    if (lane == 0 && bal) mr[g] |= bal;
                } else {
                    bool c = false;
                    int gg = 0;
                    int ty = ly - HALO, tx = lx - HALO;
                    bool inter = ((unsigned)ty < TILE) && ((unsigned)tx < TILE)
                                 && (lx < LDIM);
                    if (inter) {
                        bool fm = cond || (((oldw >> lane) & 1u) != 0u);
                        int gy = blockIdx.y*TILE + ty;
                        int gx = blockIdx.x*TILE + tx;
                        gg = gy*WW + gx;
                        out[OFF_SCORE + b*HW + gg] = sv;
                        c = fm && (sv > 0.f);
                        g_cmask[b*HW + gg] = c ? 1 : 0;
                    }
                    unsigned cb = __ballot_sync(0xffffffffu, c);
                    if (cb) {
                        int ldr = __ffs(cb) - 1;
                        int basep = 0;
                        if (lane == ldr)
                            basep = atomicAdd(&g_count[b], __popc(cb));
                        basep = __shfl_sync(0xffffffffu, basep, ldr);
                        if (c) {
                            int pos = basep + __popc(cb & ((1u << lane) - 1u));
                            if (pos < CAP) {
                                unsigned long long key =
                                    ((unsigned long long)__float_as_uint(sv) << 32)
                                    | (unsigned int)(HW - 1 - gg);
                                g_cand[b*CAP + pos] = key;
                            }
                        }
                    }
                }
            }
        }
        __syncthreads();
    }
}

// warp-aggregated histogram add (convergence-safe)
__device__ __forceinline__ void hist_add(unsigned int* h, unsigned bin,
                                         bool valid) {
    unsigned vm = __ballot_sync(0xffffffffu, valid);
    if (valid) {
        unsigned peers = __match_any_sync(vm, bin);
        int lane = threadIdx.x & 31;
        if (lane == __ffs(peers) - 1)
            atomicAdd(&h[bin], (unsigned)__popc(peers));
    }
}

// ---------------------------------------------------------------------------
// Merged threshold + select. One block per batch. NO writes to g_count here
// (reset happens in k_gather, strictly after all readers).
// Phase A: two-level 12-bit radix threshold T (zero low 40 bits => every
//          non-survivor key < every survivor key => rank among survivors
//          equals global rank).
// Phase B: compact survivors to smem, O(m^2) rank -> g_sel. Cold fallbacks.
// ---------------------------------------------------------------------------
__global__ __launch_bounds__(1024)
void k_select() {
    __shared__ unsigned int h[4096];
    __shared__ unsigned int cs[1025];
    __shared__ unsigned long long sk[SURVCAP];
    __shared__ int sBin;
    __shared__ unsigned int sAbove;
    __shared__ unsigned long long sT;
    __shared__ int scnt;
    __shared__ int sn;

    const int b = blockIdx.x;
    const int tid = threadIdx.x;
    if (tid == 0) {
        sn = min(g_count[b], CAP);
        scnt = 0;
        sT = 0ULL;
    }
    __syncthreads();
    const int n = sn;
    const unsigned int target = (unsigned int)min(n, NKPT);
    const unsigned long long* base = g_cand + (size_t)b*CAP;

    if (target > 0) {
        const int nR = (n + 1023) & ~1023;

        // ---- level 1: bins = key bits [63:52] ----
        for (int i = tid; i < 4096; i += 1024) h[i] = 0;
        if (tid == 0) cs[1024] = 0;
        __syncthreads();
        for (int i = tid; i < nR; i += 1024) {
            bool valid = i < n;
            unsigned bin = valid ? (unsigned)(base[i] >> 52) : 0u;
            hist_add(h, bin, valid);
        }
        __syncthreads();
        unsigned h0 = h[4*tid], h1 = h[4*tid+1],
                 h2 = h[4*tid+2], h3 = h[4*tid+3];
        cs[tid] = h0 + h1 + h2 + h3;
        __syncthreads();
        for (int off = 1; off < 1024; off <<= 1) {
            unsigned v = cs[tid] + ((tid + off < 1024) ? cs[tid + off] : 0u);
            __syncthreads();
            cs[tid] = v;
            __syncthreads();
        }
        {
            unsigned s4 = cs[tid + 1];
            unsigned s3 = h3 + s4, s2 = h2 + s3, s1 = h1 + s2, s0 = h0 + s1;
            unsigned sf[5] = {s0, s1, s2, s3, s4};
            #pragma unroll
            for (int i = 0; i < 4; ++i)
                if (sf[i] >= target && sf[i+1] < target) {
                    sBin = 4*tid + i; sAbove = sf[i+1];
                }
        }
        __syncthreads();
        const unsigned long long B1 = (unsigned long long)sBin;
        const unsigned int rem = target - sAbove;   // >= 1

        // ---- level 2: bins = key bits [51:40], restricted to level-1 bin ----
        __syncthreads();
        for (int i = tid; i < 4096; i += 1024) h[i] = 0;
        __syncthreads();
        for (int i = tid; i < nR; i += 1024) {
            bool valid = false;
            unsigned bin = 0;
            if (i < n) {
                unsigned long long key = base[i];
                if ((key >> 52) == B1) {
                    valid = true;
                    bin = (unsigned)(key >> 40) & 0xFFFu;
                }
            }
            hist_add(h, bin, valid);
        }
        __syncthreads();
        h0 = h[4*tid]; h1 = h[4*tid+1]; h2 = h[4*tid+2]; h3 = h[4*tid+3];
        cs[tid] = h0 + h1 + h2 + h3;
        __syncthreads();
        for (int off = 1; off < 1024; off <<= 1) {
            unsigned v = cs[tid] + ((tid + off < 1024) ? cs[tid + off] : 0u);
            __syncthreads();
            cs[tid] = v;
            __syncthreads();
        }
        {
            unsigned s4 = cs[tid + 1];
            unsigned s3 = h3 + s4, s2 = h2 + s3, s1 = h1 + s2, s0 = h0 + s1;
            unsigned sf[5] = {s0, s1, s2, s3, s4};
            #pragma unroll
            for (int i = 0; i < 4; ++i)
                if (sf[i] >= rem && sf[i+1] < rem)
                    sT = (B1 << 52) | ((unsigned long long)(4*tid + i) << 40);
        }
        __syncthreads();

        // ---- Phase B: compact survivors, rank in smem ----
        const unsigned long long T = sT;
        for (int i = tid; i < n; i += 1024) {
            unsigned long long key = base[i];
            if (key >= T) {
                int p = atomicAdd(&scnt, 1);
                if (p < SURVCAP) sk[p] = key;
            }
        }
        __syncthreads();
        int m = scnt;

        if (m <= SURVCAP) {
            for (int i = tid; i < m; i += 1024) {
                unsigned long long key = sk[i];
                int r = 0;
                for (int j = 0; j < m; ++j) r += (sk[j] > key) ? 1 : 0;
                if (r < NKPT)
                    g_sel[b*NKPT + r] = HW - 1 - (int)(key & 0xffffffffu);
            }
        } else {
            // cold: exact rank via global scans, warp per survivor
            int lane = tid & 31, w = tid >> 5;
            for (int i = w; i < n; i += 32) {
                unsigned long long key = base[i];
                if (key < T) continue;
                int r = 0;
                for (int j = lane; j < n; j += 32)
                    r += (base[j] > key) ? 1 : 0;
                #pragma unroll
                for (int off = 16; off; off >>= 1)
                    r += __shfl_down_sync(0xffffffffu, r, off);
                if (lane == 0 && r < NKPT)
                    g_sel[b*NKPT + r] = HW - 1 - (int)(key & 0xffffffffu);
            }
        }
    }

    // cold: fewer than NKPT candidates -> ascending non-candidate indices
    if (n < NKPT) {
        __syncthreads();
        if (tid == 0) {
            int slot = n;
            for (int p = 0; p < HW && slot < NKPT; ++p)
                if (!g_cmask[b*HW + p]) g_sel[b*NKPT + (slot++)] = p;
        }
    }
}

// ---------------------------------------------------------------------------
// Gather: each thread handles 4 channels of one keypoint (MLP=4 scattered
// loads), stores coalesced along k. Groups 0..BB-1 also emit kpts+pixels for
// batch = grp. Also resets g_count for the next graph replay (safe: strictly
// after k_select, sole remaining reader is next replay's k_nms atomics).
// ---------------------------------------------------------------------------
__global__ __launch_bounds__(256)
void k_gather(const float* __restrict__ bev,
              const float* __restrict__ feat,
              float* __restrict__ out) {
    int t = blockIdx.x * blockDim.x + threadIdx.x;   // 65536 threads
    if (t < BB) g_count[t] = 0;
    int k   = t & (NKPT-1);
    int grp = t >> 9;            // (b, cq): 4 * 32
    int b   = grp >> 5;
    int cq  = grp & 31;
    int idx = g_sel[b*NKPT + k];

    if (grp < BB) {  // group 'grp' emits kpts+pixels for batch 'grp'
        int bk = grp;
        int idk = g_sel[bk*NKPT + k];
        int u = idk / WW, v = idk - u*WW;
        float4 kv = make_float4(bev[(bk*7 + 3)*HW + idk],
                                bev[(bk*7 + 4)*HW + idk], 0.f, 1.f);
        ((float4*)(out + OFF_KPTS))[bk*NKPT + k] = kv;
        ((float2*)(out + OFF_PIX))[bk*NKPT + k] =
            make_float2((float)u, (float)v);
    }

    const float* fb = feat + ((size_t)(b*NFEAT + cq*4))*HW + idx;
    float v0 = fb[0*HW];
    float v1 = fb[1*HW];
    float v2 = fb[2*HW];
    float v3 = fb[3*HW];
    float* ob = out + OFF_FEAS + (size_t)(b*NFEAT + cq*4)*NKPT + k;
    ob[0*NKPT] = v0;
    ob[1*NKPT] = v1;
    ob[2*NKPT] = v2;
    ob[3*NKPT] = v3;
}

extern "C" void kernel_launch(void* const* d_in, const int* in_sizes, int n_in,
                              void* d_out, int out_size) {
    const float* bev  = (const float*)d_in[0];
    const float* raw  = (const float*)d_in[1];
    const float* feat = (const float*)d_in[2];
    float* out = (float*)d_out;

    static bool attr_set = false;
    if (!attr_set) {
        cudaFuncSetAttribute(k_nms, cudaFuncAttributeMaxDynamicSharedMemorySize,
                             NMS_SMEM);
        attr_set = true;
    }

    dim3 ngrid(WW/TILE, HH/TILE, BB);   // 8 x 8 x 4
    k_nms<<<ngrid, NMS_THREADS, NMS_SMEM>>>(bev, raw, out);
    k_select<<<BB, 1024>>>();
    k_gather<<<256, 256>>>(bev, feat, out);
}

// round 10
// speedup vs baseline: 1.0334x; 1.0334x over previous
#include <cuda_runtime.h>
#include <math_constants.h>

#define BB 4
#define HH 512
#define WW 512
#define HW (HH*WW)
#define NKPT 512
#define CAP 65536
#define NFEAT 128

#define TILE 64
#define HALO 15
#define LDIM (TILE + 2*HALO)     // 94
#define G 3                      // guard ring
#define RROWS (LDIM + 2*G)       // 100
#define SPITCH 100
#define BUF (RROWS*SPITCH)       // 10000
#define WPR 5                    // bit-words per row (slots 0,4 = zero guards)
#define NMS_SMEM (BUF*4*2 + RROWS*WPR*4*3)   // 86000 B
#define NMS_THREADS 1024
#define NMS_NW (NMS_THREADS/32)

#define SURVCAP 3072

// Output layout (float32, reference tuple order)
#define OFF_SCORE 0
#define OFF_KPTS  (BB*HW)
#define OFF_FEAS  (OFF_KPTS + BB*NKPT*4)
#define OFF_PIX   (OFF_FEAS + BB*NFEAT*NKPT)

// Scratch
__device__ unsigned long long g_cand[BB*CAP];
__device__ unsigned char g_cmask[BB*HW];
__device__ int g_count[BB];
__device__ int g_sel[BB*NKPT];

// ---------------------------------------------------------------------------
// Fused NMS. One block per 64x64 tile, 1024 threads, 2 blocks/SM (100% occ).
// Float pools in smem; mask/dilation as bitboards. Emit fused into last pass.
// ---------------------------------------------------------------------------
__global__ __launch_bounds__(NMS_THREADS, 2)
void k_nms(const float* __restrict__ bev,
           const float* __restrict__ raw,
           float* __restrict__ out) {
    extern __shared__ unsigned char smraw[];
    float* sbuf = (float*)smraw;
    float* tbuf = sbuf + BUF;
    unsigned int* mkw = (unsigned int*)(tbuf + BUF);  // max_mask bits
    unsigned int* hbw = mkw + RROWS*WPR;              // h-dilated bits
    unsigned int* spw = hbw + RROWS*WPR;              // supp (7x7 dil) bits
    float* sc = sbuf + G*SPITCH + G;
    float* tp = tbuf + G*SPITCH + G;

    const int tid  = threadIdx.x;
    const int wid  = tid >> 5;
    const int lane = tid & 31;
    const int b    = blockIdx.z;
    const int gx0  = blockIdx.x * TILE - HALO;
    const int gy0  = blockIdx.y * TILE - HALO;
    const float* g2 = bev + (b*7 + 2)*HW;
    const float* rw = raw + b*HW;

    // bit arrays + tp guard rows init
    for (int i = tid; i < RROWS*WPR; i += NMS_THREADS) {
        mkw[i] = 0; hbw[i] = 0; spw[i] = 0;
    }
    for (int i = tid; i < 6*SPITCH; i += NMS_THREADS) {
        int r = (i < 3*SPITCH) ? i : (RROWS-3)*SPITCH + (i - 3*SPITCH);
        tbuf[r] = -CUDART_INF_F;
    }

    // fused init+load over the FULL ring: gated score or -inf
    for (int r = wid; r < RROWS; r += NMS_NW) {
        int gy = gy0 + (r - G);
        const float* rwr = rw + gy*WW;
        const float* g2r = g2 + gy*WW;
        bool rowin = (unsigned)gy < HH;
        for (int col = lane; col < SPITCH; col += 32) {
            int gx = gx0 + (col - G);
            float v = -CUDART_INF_F;
            if (rowin && (unsigned)gx < WW)
                v = rwr[gx] * (g2r[gx] > 0.f ? 1.f : 0.f);
            sbuf[r*SPITCH + col] = v;
        }
    }
    __syncthreads();

    // P1: h 7-max sc -> tp
    for (int ly = wid; ly < LDIM; ly += NMS_NW) {
        const float* row = sc + ly*SPITCH;
        for (int lx = lane; lx < LDIM; lx += 32) {
            float m = row[lx-3];
            #pragma unroll
            for (int k = -2; k <= 3; ++k) m = fmaxf(m, row[lx+k]);
            tp[ly*SPITCH + lx] = m;
        }
    }
    __syncthreads();
    // P2: v 7-max of tp; mk bit = (max == sc) & in-image
    for (int ly = wid; ly < LDIM; ly += NMS_NW) {
        for (int g = 0; g < 3; ++g) {
            int lx = g*32 + lane;
            bool pred = false;
            if (lx < LDIM) {
                const float* col = tp + ly*SPITCH + lx;
                float m = col[-3*SPITCH];
                #pragma unroll
                for (int k = -2; k <= 3; ++k) m = fmaxf(m, col[k*SPITCH]);
                float sv = sc[ly*SPITCH + lx];
                pred = (m == sv && sv >= 0.f);
            }
            unsigned bal = __ballot_sync(0xffffffffu, pred);
            if (lane == 0) mkw[(ly+G)*WPR + 1 + g] = bal;
        }
    }
    __syncthreads();

    for (int it = 0; it < 2; ++it) {
        // P3: h-dilate mk bits
        for (int t = tid; t < 300; t += NMS_THREADS) {
            int row = t / 3, w = t % 3 + 1;
            const unsigned int* mr = mkw + row*WPR;
            unsigned a = mr[w-1], c = mr[w], d = mr[w+1];
            unsigned res = c;
            res |= __funnelshift_l(a, c, 1) | __funnelshift_r(c, d, 1);
            res |= __funnelshift_l(a, c, 2) | __funnelshift_r(c, d, 2);
            res |= __funnelshift_l(a, c, 3) | __funnelshift_r(c, d, 3);
            hbw[row*WPR + w] = res;
        }
        __syncthreads();
        // P4: v-dilate
        for (int t = tid; t < 282; t += NMS_THREADS) {
            int row = t / 3 + 3, w = t % 3 + 1;
            unsigned r = 0;
            #pragma unroll
            for (int k = -3; k <= 3; ++k) r |= hbw[(row+k)*WPR + w];
            spw[row*WPR + w] = r;
        }
        __syncthreads();
        // P5: h 7-max of (supbit ? 0 : sc) -> tp
        for (int ly = wid; ly < LDIM; ly += NMS_NW) {
            const float* srow = sc + ly*SPITCH;
            const unsigned int* sr = spw + (ly+G)*WPR + 1;
            for (int lx = lane; lx < LDIM; lx += 32) {
                float m = -CUDART_INF_F;
                #pragma unroll
                for (int k = -3; k <= 3; ++k) {
                    int B = lx + k;
                    unsigned wv = sr[B >> 5];
                    float v = ((wv >> (B & 31)) & 1u) ? 0.f : srow[lx+k];
                    m = fmaxf(m, v);
                }
                tp[ly*SPITCH + lx] = m;
            }
        }
        __syncthreads();
        // P6: v 7-max of tp; cond = (!sup & sv>=0 & m==sv)
        for (int ly = wid; ly < LDIM; ly += NMS_NW) {
            const unsigned int* sr = spw + (ly+G)*WPR + 1;
            unsigned int* mr = mkw + (ly+G)*WPR + 1;
            for (int g = 0; g < 3; ++g) {
                int lx = g*32 + lane;
                bool cond = false;
                float sv = 0.f;
                unsigned oldw = mr[g];
                if (lx < LDIM) {
                    const float* col = tp + ly*SPITCH + lx;
                    float m = col[-3*SPITCH];
                    #pragma unroll
                    for (int k = -2; k <= 3; ++k) m = fmaxf(m, col[k*SPITCH]);
                    sv = sc[ly*SPITCH + lx];
                    unsigned supb = (sr[g] >> lane) & 1u;
                    cond = (!supb && sv >= 0.f && m == sv);
                }
                if (it == 0) {
                    unsigned bal = __ballot_sync(0xffffffffu, cond);
                    if (lane == 0 && bal) mr[g] |= bal;
                } else {
                    bool c = false;
                    int gg = 0;
                    int ty = ly - HALO, tx = lx - HALO;
                    bool inter = ((unsigned)ty < TILE) && ((unsigned)tx < TILE)
                                 && (lx < LDIM);
                    if (inter) {
                        bool fm = cond || (((oldw >> lane) & 1u) != 0u);
                        int gy = blockIdx.y*TILE + ty;
                        int gx = blockIdx.x*TILE + tx;
                        gg = gy*WW + gx;
                        out[OFF_SCORE + b*HW + gg] = sv;
                        c = fm && (sv > 0.f);
                        g_cmask[b*HW + gg] = c ? 1 : 0;
                    }
                    unsigned cb = __ballot_sync(0xffffffffu, c);
                    if (cb) {
                        int ldr = __ffs(cb) - 1;
                        int basep = 0;
                        if (lane == ldr)
                            basep = atomicAdd(&g_count[b], __popc(cb));
                        basep = __shfl_sync(0xffffffffu, basep, ldr);
                        if (c) {
                            int pos = basep + __popc(cb & ((1u << lane) - 1u));
                            if (pos < CAP) {
                                unsigned long long key =
                                    ((unsigned long long)__float_as_uint(sv) << 32)
                                    | (unsigned int)(HW - 1 - gg);
                                g_cand[b*CAP + pos] = key;
                            }
                        }
                    }
                }
            }
        }
        __syncthreads();
    }
}

// warp-aggregated histogram add (convergence-safe)
__device__ __forceinline__ void hist_add(unsigned int* h, unsigned bin,
                                         bool valid) {
    unsigned vm = __ballot_sync(0xffffffffu, valid);
    if (valid) {
        unsigned peers = __match_any_sync(vm, bin);
        int lane = threadIdx.x & 31;
        if (lane == __ffs(peers) - 1)
            atomicAdd(&h[bin], (unsigned)__popc(peers));
    }
}

// ---------------------------------------------------------------------------
// Merged threshold + select. One block per batch. NO writes to g_count here
// (reset happens in k_gather, strictly after all readers).
// ---------------------------------------------------------------------------
__global__ __launch_bounds__(1024)
void k_select() {
    __shared__ unsigned int h[4096];
    __shared__ unsigned int cs[1025];
    __shared__ unsigned long long sk[SURVCAP];
    __shared__ int sBin;
    __shared__ unsigned int sAbove;
    __shared__ unsigned long long sT;
    __shared__ int scnt;
    __shared__ int sn;

    const int b = blockIdx.x;
    const int tid = threadIdx.x;
    if (tid == 0) {
        sn = min(g_count[b], CAP);
        scnt = 0;
        sT = 0ULL;
    }
    __syncthreads();
    const int n = sn;
    const unsigned int target = (unsigned int)min(n, NKPT);
    const unsigned long long* base = g_cand + (size_t)b*CAP;

    if (target > 0) {
        const int nR = (n + 1023) & ~1023;

        // ---- level 1: bins = key bits [63:52] ----
        for (int i = tid; i < 4096; i += 1024) h[i] = 0;
        if (tid == 0) cs[1024] = 0;
        __syncthreads();
        for (int i = tid; i < nR; i += 1024) {
            bool valid = i < n;
            unsigned bin = valid ? (unsigned)(base[i] >> 52) : 0u;
            hist_add(h, bin, valid);
        }
        __syncthreads();
        unsigned h0 = h[4*tid], h1 = h[4*tid+1],
                 h2 = h[4*tid+2], h3 = h[4*tid+3];
        cs[tid] = h0 + h1 + h2 + h3;
        __syncthreads();
        for (int off = 1; off < 1024; off <<= 1) {
            unsigned v = cs[tid] + ((tid + off < 1024) ? cs[tid + off] : 0u);
            __syncthreads();
            cs[tid] = v;
            __syncthreads();
        }
        {
            unsigned s4 = cs[tid + 1];
            unsigned s3 = h3 + s4, s2 = h2 + s3, s1 = h1 + s2, s0 = h0 + s1;
            unsigned sf[5] = {s0, s1, s2, s3, s4};
            #pragma unroll
            for (int i = 0; i < 4; ++i)
                if (sf[i] >= target && sf[i+1] < target) {
                    sBin = 4*tid + i; sAbove = sf[i+1];
                }
        }
        __syncthreads();
        const unsigned long long B1 = (unsigned long long)sBin;
        const unsigned int rem = target - sAbove;   // >= 1

        // ---- level 2: bins = key bits [51:40], restricted to level-1 bin ----
        __syncthreads();
        for (int i = tid; i < 4096; i += 1024) h[i] = 0;
        __syncthreads();
        for (int i = tid; i < nR; i += 1024) {
            bool valid = false;
            unsigned bin = 0;
            if (i < n) {
                unsigned long long key = base[i];
                if ((key >> 52) == B1) {
                    valid = true;
                    bin = (unsigned)(key >> 40) & 0xFFFu;
                }
            }
            hist_add(h, bin, valid);
        }
        __syncthreads();
        h0 = h[4*tid]; h1 = h[4*tid+1]; h2 = h[4*tid+2]; h3 = h[4*tid+3];
        cs[tid] = h0 + h1 + h2 + h3;
        __syncthreads();
        for (int off = 1; off < 1024; off <<= 1) {
            unsigned v = cs[tid] + ((tid + off < 1024) ? cs[tid + off] : 0u);
            __syncthreads();
            cs[tid] = v;
            __syncthreads();
        }
        {
            unsigned s4 = cs[tid + 1];
            unsigned s3 = h3 + s4, s2 = h2 + s3, s1 = h1 + s2, s0 = h0 + s1;
            unsigned sf[5] = {s0, s1, s2, s3, s4};
            #pragma unroll
            for (int i = 0; i < 4; ++i)
                if (sf[i] >= rem && sf[i+1] < rem)
                    sT = (B1 << 52) | ((unsigned long long)(4*tid + i) << 40);
        }
        __syncthreads();

        // ---- Phase B: compact survivors, rank in smem ----
        const unsigned long long T = sT;
        for (int i = tid; i < n; i += 1024) {
            unsigned long long key = base[i];
            if (key >= T) {
                int p = atomicAdd(&scnt, 1);
                if (p < SURVCAP) sk[p] = key;
            }
        }
        __syncthreads();
        int m = scnt;

        if (m <= SURVCAP) {
            for (int i = tid; i < m; i += 1024) {
                unsigned long long key = sk[i];
                int r = 0;
                for (int j = 0; j < m; ++j) r += (sk[j] > key) ? 1 : 0;
                if (r < NKPT)
                    g_sel[b*NKPT + r] = HW - 1 - (int)(key & 0xffffffffu);
            }
        } else {
            // cold: exact rank via global scans, warp per survivor
            int lane = tid & 31, w = tid >> 5;
            for (int i = w; i < n; i += 32) {
                unsigned long long key = base[i];
                if (key < T) continue;
                int r = 0;
                for (int j = lane; j < n; j += 32)
                    r += (base[j] > key) ? 1 : 0;
                #pragma unroll
                for (int off = 16; off; off >>= 1)
                    r += __shfl_down_sync(0xffffffffu, r, off);
                if (lane == 0 && r < NKPT)
                    g_sel[b*NKPT + r] = HW - 1 - (int)(key & 0xffffffffu);
            }
        }
    }

    // cold: fewer than NKPT candidates -> ascending non-candidate indices
    if (n < NKPT) {
        __syncthreads();
        if (tid == 0) {
            int slot = n;
            for (int p = 0; p < HW && slot < NKPT; ++p)
                if (!g_cmask[b*HW + p]) g_sel[b*NKPT + (slot++)] = p;
        }
    }
}

// ---------------------------------------------------------------------------
// Gather: each thread handles 8 channels of one keypoint (MLP=8 scattered
// loads), stores coalesced along k. Groups 0..BB-1 also emit kpts+pixels.
// Resets g_count for the next graph replay (strictly after k_select).
// ---------------------------------------------------------------------------
__global__ __launch_bounds__(256)
void k_gather(const float* __restrict__ bev,
              const float* __restrict__ feat,
              float* __restrict__ out) {
    int t = blockIdx.x * blockDim.x + threadIdx.x;   // 32768 threads
    if (t < BB) g_count[t] = 0;
    int k   = t & (NKPT-1);
    int grp = t >> 9;            // (b, cq): 4 * 16
    int b   = grp >> 4;
    int cq  = grp & 15;
    int idx = g_sel[b*NKPT + k];

    if (grp < BB) {  // group 'grp' emits kpts+pixels for batch 'grp'
        int bk = grp;
        int idk = g_sel[bk*NKPT + k];
        int u = idk / WW, v = idk - u*WW;
        float4 kv = make_float4(bev[(bk*7 + 3)*HW + idk],
                                bev[(bk*7 + 4)*HW + idk], 0.f, 1.f);
        ((float4*)(out + OFF_KPTS))[bk*NKPT + k] = kv;
        ((float2*)(out + OFF_PIX))[bk*NKPT + k] =
            make_float2((float)u, (float)v);
    }

    const float* fb = feat + ((size_t)(b*NFEAT + cq*8))*HW + idx;
    float v0 = fb[0*HW];
    float v1 = fb[1*HW];
    float v2 = fb[2*HW];
    float v3 = fb[3*HW];
    float v4 = fb[4*HW];
    float v5 = fb[5*HW];
    float v6 = fb[6*HW];
    float v7 = fb[7*HW];
    float* ob = out + OFF_FEAS + (size_t)(b*NFEAT + cq*8)*NKPT + k;
    ob[0*NKPT] = v0;
    ob[1*NKPT] = v1;
    ob[2*NKPT] = v2;
    ob[3*NKPT] = v3;
    ob[4*NKPT] = v4;
    ob[5*NKPT] = v5;
    ob[6*NKPT] = v6;
    ob[7*NKPT] = v7;
}

extern "C" void kernel_launch(void* const* d_in, const int* in_sizes, int n_in,
                              void* d_out, int out_size) {
    const float* bev  = (const float*)d_in[0];
    const float* raw  = (const float*)d_in[1];
    const float* feat = (const float*)d_in[2];
    float* out = (float*)d_out;

    static bool attr_set = false;
    if (!attr_set) {
        cudaFuncSetAttribute(k_nms, cudaFuncAttributeMaxDynamicSharedMemorySize,
                             NMS_SMEM);
        attr_set = true;
    }

    dim3 ngrid(WW/TILE, HH/TILE, BB);   // 8 x 8 x 4
    k_nms<<<ngrid, NMS_THREADS, NMS_SMEM>>>(bev, raw, out);
    k_select<<<BB, 1024>>>();
    k_gather<<<128, 256>>>(bev, feat, out);
}

// round 11
// speedup vs baseline: 1.1318x; 1.0952x over previous
#include <cuda_runtime.h>
#include <math_constants.h>

#define BB 4
#define HH 512
#define WW 512
#define HW (HH*WW)
#define NKPT 512
#define CAP 65536
#define NFEAT 128

#define TILE 64
#define HALO 15
#define LDIM (TILE + 2*HALO)     // 94
#define GR 3                     // guard rows (top/bottom)
#define GC 4                     // guard cols left (4 for float2 alignment)
#define RROWS (LDIM + 2*GR)      // 100
#define SPITCH 104               // 4 left guard + 94 + 6 right guard/pad
#define BUF (RROWS*SPITCH)       // 10400
#define WPR 5                    // bit-words per row (slots 0,4 = zero guards)
#define NMS_SMEM (BUF*4*2 + RROWS*WPR*4*3)   // 89200 B
#define NMS_THREADS 1024
#define NMS_NW (NMS_THREADS/32)
#define NPAIR 47                 // 94/2 pixel pairs per row

#define SURVCAP 3072

// Output layout (float32, reference tuple order)
#define OFF_SCORE 0
#define OFF_KPTS  (BB*HW)
#define OFF_FEAS  (OFF_KPTS + BB*NKPT*4)
#define OFF_PIX   (OFF_FEAS + BB*NFEAT*NKPT)

// Scratch
__device__ unsigned long long g_cand[BB*CAP];
__device__ unsigned char g_cmask[BB*HW];
__device__ int g_count[BB];
__device__ int g_sel[BB*NKPT];

// ---------------------------------------------------------------------------
// Fused NMS. One block per 64x64 tile, 1024 threads, 2 blocks/SM.
// H-pool passes (P1, P5) are float2 pair-vectorized; P5 suppression bits come
// from one funnel-shift window per pair. P2/P6 scalar (ballot layout intact).
// ---------------------------------------------------------------------------
__global__ __launch_bounds__(NMS_THREADS, 2)
void k_nms(const float* __restrict__ bev,
           const float* __restrict__ raw,
           float* __restrict__ out) {
    extern __shared__ unsigned char smraw[];
    float* sbuf = (float*)smraw;
    float* tbuf = sbuf + BUF;
    unsigned int* mkw = (unsigned int*)(tbuf + BUF);  // max_mask bits
    unsigned int* hbw = mkw + RROWS*WPR;              // h-dilated bits
    unsigned int* spw = hbw + RROWS*WPR;              // supp (7x7 dil) bits
    float* sc = sbuf + GR*SPITCH + GC;
    float* tp = tbuf + GR*SPITCH + GC;

    const int tid  = threadIdx.x;
    const int wid  = tid >> 5;
    const int lane = tid & 31;
    const int b    = blockIdx.z;
    const int gx0  = blockIdx.x * TILE - HALO;
    const int gy0  = blockIdx.y * TILE - HALO;
    const float* g2 = bev + (b*7 + 2)*HW;
    const float* rw = raw + b*HW;

    // bit arrays + tp guard rows init
    for (int i = tid; i < RROWS*WPR; i += NMS_THREADS) {
        mkw[i] = 0; hbw[i] = 0; spw[i] = 0;
    }
    for (int i = tid; i < 6*SPITCH; i += NMS_THREADS) {
        int r = (i < 3*SPITCH) ? i : (RROWS-3)*SPITCH + (i - 3*SPITCH);
        tbuf[r] = -CUDART_INF_F;
    }

    // fused init+load over the FULL ring: gated score or -inf
    for (int r = wid; r < RROWS; r += NMS_NW) {
        int gy = gy0 + (r - GR);
        const float* rwr = rw + gy*WW;
        const float* g2r = g2 + gy*WW;
        bool rowin = (unsigned)gy < HH;
        for (int col = lane; col < SPITCH; col += 32) {
            int gx = gx0 + (col - GC);
            float v = -CUDART_INF_F;
            if (rowin && (unsigned)gx < WW)
                v = rwr[gx] * (g2r[gx] > 0.f ? 1.f : 0.f);
            sbuf[r*SPITCH + col] = v;
        }
    }
    __syncthreads();

    // P1: h 7-max sc -> tp (pair-vectorized)
    for (int ly = wid; ly < LDIM; ly += NMS_NW) {
        const float* row = sc + ly*SPITCH;
        float* trow = tp + ly*SPITCH;
        for (int p2 = lane; p2 < NPAIR; p2 += 32) {
            int x = p2*2;
            float2 a = *(const float2*)(row + x - 4);
            float2 bb = *(const float2*)(row + x - 2);
            float2 c = *(const float2*)(row + x);
            float2 d = *(const float2*)(row + x + 2);
            float2 e = *(const float2*)(row + x + 4);
            float ms = fmaxf(fmaxf(fmaxf(bb.x, bb.y), fmaxf(c.x, c.y)),
                             fmaxf(d.x, d.y));
            float m0 = fmaxf(ms, a.y);
            float m1 = fmaxf(ms, e.x);
            *(float2*)(trow + x) = make_float2(m0, m1);
        }
    }
    __syncthreads();
    // P2: v 7-max of tp; mk bit = (max == sc) & in-image (scalar, ballot)
    for (int ly = wid; ly < LDIM; ly += NMS_NW) {
        for (int g = 0; g < 3; ++g) {
            int lx = g*32 + lane;
            bool pred = false;
            if (lx < LDIM) {
                const float* col = tp + ly*SPITCH + lx;
                float m = col[-3*SPITCH];
                #pragma unroll
                for (int k = -2; k <= 3; ++k) m = fmaxf(m, col[k*SPITCH]);
                float sv = sc[ly*SPITCH + lx];
                pred = (m == sv && sv >= 0.f);
            }
            unsigned bal = __ballot_sync(0xffffffffu, pred);
            if (lane == 0) mkw[(ly+GR)*WPR + 1 + g] = bal;
        }
    }
    __syncthreads();

    for (int it = 0; it < 2; ++it) {
        // P3: h-dilate mk bits
        for (int t = tid; t < 300; t += NMS_THREADS) {
            int row = t / 3, w = t % 3 + 1;
            const unsigned int* mr = mkw + row*WPR;
            unsigned a = mr[w-1], c = mr[w], d = mr[w+1];
            unsigned res = c;
            res |= __funnelshift_l(a, c, 1) | __funnelshift_r(c, d, 1);
            res |= __funnelshift_l(a, c, 2) | __funnelshift_r(c, d, 2);
            res |= __funnelshift_l(a, c, 3) | __funnelshift_r(c, d, 3);
            hbw[row*WPR + w] = res;
        }
        __syncthreads();
        // P4: v-dilate
        for (int t = tid; t < 282; t += NMS_THREADS) {
            int row = t / 3 + 3, w = t % 3 + 1;
            unsigned r = 0;
            #pragma unroll
            for (int k = -3; k <= 3; ++k) r |= hbw[(row+k)*WPR + w];
            spw[row*WPR + w] = r;
        }
        __syncthreads();
        // P5: h 7-max of (supbit ? 0 : sc) -> tp (pair-vectorized)
        for (int ly = wid; ly < LDIM; ly += NMS_NW) {
            const float* row = sc + ly*SPITCH;
            float* trow = tp + ly*SPITCH;
            const unsigned int* srG = spw + (ly+GR)*WPR;  // word0 = bits -32..-1
            for (int p2 = lane; p2 < NPAIR; p2 += 32) {
                int x = p2*2;
                int Bp = x + 29;                 // (x-3) + 32
                unsigned w0 = srG[Bp >> 5];
                unsigned w1 = srG[(Bp >> 5) + 1];
                unsigned win = __funnelshift_r(w0, w1, Bp & 31);
                float2 a = *(const float2*)(row + x - 4);
                float2 bb = *(const float2*)(row + x - 2);
                float2 c = *(const float2*)(row + x);
                float2 d = *(const float2*)(row + x + 2);
                float2 e = *(const float2*)(row + x + 4);
                float s0 = (win & 1u)   ? 0.f : a.y;
                float s1 = (win & 2u)   ? 0.f : bb.x;
                float s2 = (win & 4u)   ? 0.f : bb.y;
                float s3 = (win & 8u)   ? 0.f : c.x;
                float s4 = (win & 16u)  ? 0.f : c.y;
                float s5 = (win & 32u)  ? 0.f : d.x;
                float s6 = (win & 64u)  ? 0.f : d.y;
                float s7 = (win & 128u) ? 0.f : e.x;
                float ms = fmaxf(fmaxf(fmaxf(s1, s2), fmaxf(s3, s4)),
                                 fmaxf(s5, s6));
                float m0 = fmaxf(ms, s0);
                float m1 = fmaxf(ms, s7);
                *(float2*)(trow + x) = make_float2(m0, m1);
            }
        }
        __syncthreads();
        // P6: v 7-max of tp; cond = (!sup & sv>=0 & m==sv)  (scalar)
        for (int ly = wid; ly < LDIM; ly += NMS_NW) {
            const unsigned int* sr = spw + (ly+GR)*WPR + 1;
            unsigned int* mr = mkw + (ly+GR)*WPR + 1;
            for (int g = 0; g < 3; ++g) {
                int lx = g*32 + lane;
                bool cond = false;
                float sv = 0.f;
                unsigned oldw = mr[g];
                if (lx < LDIM) {
                    const float* col = tp + ly*SPITCH + lx;
                    float m = col[-3*SPITCH];
                    #pragma unroll
                    for (int k = -2; k <= 3; ++k) m = fmaxf(m, col[k*SPITCH]);
                    sv = sc[ly*SPITCH + lx];
                    unsigned supb = (sr[g] >> lane) & 1u;
                    cond = (!supb && sv >= 0.f && m == sv);
                }
                if (it == 0) {
                    unsigned bal = __ballot_sync(0xffffffffu, cond);
                    if (lane == 0 && bal) mr[g] |= bal;
                } else {
                    bool c = false;
                    int gg = 0;
                    int ty = ly - HALO, tx = lx - HALO;
                    bool inter = ((unsigned)ty < TILE) && ((unsigned)tx < TILE)
                                 && (lx < LDIM);
                    if (inter) {
                        bool fm = cond || (((oldw >> lane) & 1u) != 0u);
                        int gy = blockIdx.y*TILE + ty;
                        int gx = blockIdx.x*TILE + tx;
                        gg = gy*WW + gx;
                        out[OFF_SCORE + b*HW + gg] = sv;
                        c = fm && (sv > 0.f);
                        g_cmask[b*HW + gg] = c ? 1 : 0;
                    }
                    unsigned cb = __ballot_sync(0xffffffffu, c);
                    if (cb) {
                        int ldr = __ffs(cb) - 1;
                        int basep = 0;
                        if (lane == ldr)
                            basep = atomicAdd(&g_count[b], __popc(cb));
                        basep = __shfl_sync(0xffffffffu, basep, ldr);
                        if (c) {
                            int pos = basep + __popc(cb & ((1u << lane) - 1u));
                            if (pos < CAP) {
                                unsigned long long key =
                                    ((unsigned long long)__float_as_uint(sv) << 32)
                                    | (unsigned int)(HW - 1 - gg);
                                g_cand[b*CAP + pos] = key;
                            }
                        }
                    }
                }
            }
        }
        __syncthreads();
    }
}

// warp-aggregated histogram add (convergence-safe)
__device__ __forceinline__ void hist_add(unsigned int* h, unsigned bin,
                                         bool valid) {
    unsigned vm = __ballot_sync(0xffffffffu, valid);
    if (valid) {
        unsigned peers = __match_any_sync(vm, bin);
        int lane = threadIdx.x & 31;
        if (lane == __ffs(peers) - 1)
            atomicAdd(&h[bin], (unsigned)__popc(peers));
    }
}

// ---------------------------------------------------------------------------
// Merged threshold + select. One block per batch. NO writes to g_count here
// (reset happens in k_gather, strictly after all readers).
// ---------------------------------------------------------------------------
__global__ __launch_bounds__(1024)
void k_select() {
    __shared__ unsigned int h[4096];
    __shared__ unsigned int cs[1025];
    __shared__ unsigned long long sk[SURVCAP];
    __shared__ int sBin;
    __shared__ unsigned int sAbove;
    __shared__ unsigned long long sT;
    __shared__ int scnt;
    __shared__ int sn;

    const int b = blockIdx.x;
    const int tid = threadIdx.x;
    if (tid == 0) {
        sn = min(g_count[b], CAP);
        scnt = 0;
        sT = 0ULL;
    }
    __syncthreads();
    const int n = sn;
    const unsigned int target = (unsigned int)min(n, NKPT);
    const unsigned long long* base = g_cand + (size_t)b*CAP;

    if (target > 0) {
        const int nR = (n + 1023) & ~1023;

        // ---- level 1: bins = key bits [63:52] ----
        for (int i = tid; i < 4096; i += 1024) h[i] = 0;
        if (tid == 0) cs[1024] = 0;
        __syncthreads();
        for (int i = tid; i < nR; i += 1024) {
            bool valid = i < n;
            unsigned bin = valid ? (unsigned)(base[i] >> 52) : 0u;
            hist_add(h, bin, valid);
        }
        __syncthreads();
        unsigned h0 = h[4*tid], h1 = h[4*tid+1],
                 h2 = h[4*tid+2], h3 = h[4*tid+3];
        cs[tid] = h0 + h1 + h2 + h3;
        __syncthreads();
        for (int off = 1; off < 1024; off <<= 1) {
            unsigned v = cs[tid] + ((tid + off < 1024) ? cs[tid + off] : 0u);
            __syncthreads();
            cs[tid] = v;
            __syncthreads();
        }
        {
            unsigned s4 = cs[tid + 1];
            unsigned s3 = h3 + s4, s2 = h2 + s3, s1 = h1 + s2, s0 = h0 + s1;
            unsigned sf[5] = {s0, s1, s2, s3, s4};
            #pragma unroll
            for (int i = 0; i < 4; ++i)
                if (sf[i] >= target && sf[i+1] < target) {
                    sBin = 4*tid + i; sAbove = sf[i+1];
                }
        }
        __syncthreads();
        const unsigned long long B1 = (unsigned long long)sBin;
        const unsigned int rem = target - sAbove;   // >= 1

        // ---- level 2: bins = key bits [51:40], restricted to level-1 bin ----
        __syncthreads();
        for (int i = tid; i < 4096; i += 1024) h[i] = 0;
        __syncthreads();
        for (int i = tid; i < nR; i += 1024) {
            bool valid = false;
            unsigned bin = 0;
            if (i < n) {
                unsigned long long key = base[i];
                if ((key >> 52) == B1) {
                    valid = true;
                    bin = (unsigned)(key >> 40) & 0xFFFu;
                }
            }
            hist_add(h, bin, valid);
        }
        __syncthreads();
        h0 = h[4*tid]; h1 = h[4*tid+1]; h2 = h[4*tid+2]; h3 = h[4*tid+3];
        cs[tid] = h0 + h1 + h2 + h3;
        __syncthreads();
        for (int off = 1; off < 1024; off <<= 1) {
            unsigned v = cs[tid] + ((tid + off < 1024) ? cs[tid + off] : 0u);
            __syncthreads();
            cs[tid] = v;
            __syncthreads();
        }
        {
            unsigned s4 = cs[tid + 1];
            unsigned s3 = h3 + s4, s2 = h2 + s3, s1 = h1 + s2, s0 = h0 + s1;
            unsigned sf[5] = {s0, s1, s2, s3, s4};
            #pragma unroll
            for (int i = 0; i < 4; ++i)
                if (sf[i] >= rem && sf[i+1] < rem)
                    sT = (B1 << 52) | ((unsigned long long)(4*tid + i) << 40);
        }
        __syncthreads();

        // ---- Phase B: compact survivors, rank in smem ----
        const unsigned long long T = sT;
        for (int i = tid; i < n; i += 1024) {
            unsigned long long key = base[i];
            if (key >= T) {
                int p = atomicAdd(&scnt, 1);
                if (p < SURVCAP) sk[p] = key;
            }
        }
        __syncthreads();
        int m = scnt;

        if (m <= SURVCAP) {
            for (int i = tid; i < m; i += 1024) {
                unsigned long long key = sk[i];
                int r = 0;
                for (int j = 0; j < m; ++j) r += (sk[j] > key) ? 1 : 0;
                if (r < NKPT)
                    g_sel[b*NKPT + r] = HW - 1 - (int)(key & 0xffffffffu);
            }
        } else {
            // cold: exact rank via global scans, warp per survivor
            int lane = tid & 31, w = tid >> 5;
            for (int i = w; i < n; i += 32) {
                unsigned long long key = base[i];
                if (key < T) continue;
                int r = 0;
                for (int j = lane; j < n; j += 32)
                    r += (base[j] > key) ? 1 : 0;
                #pragma unroll
                for (int off = 16; off; off >>= 1)
                    r += __shfl_down_sync(0xffffffffu, r, off);
                if (lane == 0 && r < NKPT)
                    g_sel[b*NKPT + r] = HW - 1 - (int)(key & 0xffffffffu);
            }
        }
    }

    // cold: fewer than NKPT candidates -> ascending non-candidate indices
    if (n < NKPT) {
        __syncthreads();
        if (tid == 0) {
            int slot = n;
            for (int p = 0; p < HW && slot < NKPT; ++p)
                if (!g_cmask[b*HW + p]) g_sel[b*NKPT + (slot++)] = p;
        }
    }
}

// ---------------------------------------------------------------------------
// Gather: each thread handles 8 channels of one keypoint (MLP=8 scattered
// loads), stores coalesced along k. Groups 0..BB-1 also emit kpts+pixels.
// Resets g_count for the next graph replay (strictly after k_select).
// ---------------------------------------------------------------------------
__global__ __launch_bounds__(256)
void k_gather(const float* __restrict__ bev,
              const float* __restrict__ feat,
              float* __restrict__ out) {
    int t = blockIdx.x * blockDim.x + threadIdx.x;   // 32768 threads
    if (t < BB) g_count[t] = 0;
    int k   = t & (NKPT-1);
    int grp = t >> 9;            // (b, cq): 4 * 16
    int b   = grp >> 4;
    int cq  = grp & 15;
    int idx = g_sel[b*NKPT + k];

    if (grp < BB) {  // group 'grp' emits kpts+pixels for batch 'grp'
        int bk = grp;
        int idk = g_sel[bk*NKPT + k];
        int u = idk / WW, v = idk - u*WW;
        float4 kv = make_float4(bev[(bk*7 + 3)*HW + idk],
                                bev[(bk*7 + 4)*HW + idk], 0.f, 1.f);
        ((float4*)(out + OFF_KPTS))[bk*NKPT + k] = kv;
        ((float2*)(out + OFF_PIX))[bk*NKPT + k] =
            make_float2((float)u, (float)v);
    }

    const float* fb = feat + ((size_t)(b*NFEAT + cq*8))*HW + idx;
    float v0 = fb[0*HW];
    float v1 = fb[1*HW];
    float v2 = fb[2*HW];
    float v3 = fb[3*HW];
    float v4 = fb[4*HW];
    float v5 = fb[5*HW];
    float v6 = fb[6*HW];
    float v7 = fb[7*HW];
    float* ob = out + OFF_FEAS + (size_t)(b*NFEAT + cq*8)*NKPT + k;
    ob[0*NKPT] = v0;
    ob[1*NKPT] = v1;
    ob[2*NKPT] = v2;
    ob[3*NKPT] = v3;
    ob[4*NKPT] = v4;
    ob[5*NKPT] = v5;
    ob[6*NKPT] = v6;
    ob[7*NKPT] = v7;
}

extern "C" void kernel_launch(void* const* d_in, const int* in_sizes, int n_in,
                              void* d_out, int out_size) {
    const float* bev  = (const float*)d_in[0];
    const float* raw  = (const float*)d_in[1];
    const float* feat = (const float*)d_in[2];
    float* out = (float*)d_out;

    static bool attr_set = false;
    if (!attr_set) {
        cudaFuncSetAttribute(k_nms, cudaFuncAttributeMaxDynamicSharedMemorySize,
                             NMS_SMEM);
        attr_set = true;
    }

    dim3 ngrid(WW/TILE, HH/TILE, BB);   // 8 x 8 x 4
    k_nms<<<ngrid, NMS_THREADS, NMS_SMEM>>>(bev, raw, out);
    k_select<<<BB, 1024>>>();
    k_gather<<<128, 256>>>(bev, feat, out);
}

// round 12
// speedup vs baseline: 1.1741x; 1.0374x over previous
#include <cuda_runtime.h>
#include <math_constants.h>

#define BB 4
#define HH 512
#define WW 512
#define HW (HH*WW)
#define NKPT 512
#define CAP 65536
#define NFEAT 128

#define TILE 64
#define HALO 15
#define LDIM (TILE + 2*HALO)     // 94
#define GR 3                     // guard rows (top/bottom)
#define GC 4                     // guard cols left (16B alignment)
#define RROWS (LDIM + 2*GR)      // 100
#define SPITCH 104
#define BUF (RROWS*SPITCH)       // 10400
#define WPR 5                    // bit-words per row (slots 0,4 = zero guards)
#define NMS_SMEM (BUF*4*2 + RROWS*WPR*4*3)   // 89200 B
#define NMS_THREADS 1024
#define NMS_NW (NMS_THREADS/32)

#define SURVCAP 3072

// Output layout (float32, reference tuple order)
#define OFF_SCORE 0
#define OFF_KPTS  (BB*HW)
#define OFF_FEAS  (OFF_KPTS + BB*NKPT*4)
#define OFF_PIX   (OFF_FEAS + BB*NFEAT*NKPT)

// Scratch
__device__ unsigned long long g_cand[BB*CAP];
__device__ unsigned char g_cmask[BB*HW];
__device__ int g_count[BB];
__device__ int g_sel[BB*NKPT];

// quad h-pool of suppressed scores: compile-time region for magic-div
template<int R0, int NR, int Q0, int NQt>
__device__ __forceinline__ void p5_quads(const float* __restrict__ sc,
                                         float* __restrict__ tp,
                                         const unsigned int* __restrict__ spw,
                                         int tid) {
    for (int t = tid; t < NR*NQt; t += NMS_THREADS) {
        int ly = R0 + t / NQt;
        int x  = (Q0 + t % NQt) << 2;
        const float* row = sc + ly*SPITCH;
        const unsigned int* srG = spw + (ly+GR)*WPR;  // word0 = bits -32..-1
        int Bp = x + 29;                              // (x-3) + 32
        unsigned w0 = srG[Bp >> 5];
        unsigned w1 = srG[(Bp >> 5) + 1];
        unsigned win = __funnelshift_r(w0, w1, Bp);
        float4 a = *(const float4*)(row + x - 4);
        float4 c = *(const float4*)(row + x);
        float4 e = *(const float4*)(row + x + 4);
        float s0 = (win & 1u)    ? 0.f : a.y;
        float s1 = (win & 2u)    ? 0.f : a.z;
        float s2 = (win & 4u)    ? 0.f : a.w;
        float s3 = (win & 8u)    ? 0.f : c.x;
        float s4 = (win & 16u)   ? 0.f : c.y;
        float s5 = (win & 32u)   ? 0.f : c.z;
        float s6 = (win & 64u)   ? 0.f : c.w;
        float s7 = (win & 128u)  ? 0.f : e.x;
        float s8 = (win & 256u)  ? 0.f : e.y;
        float s9 = (win & 512u)  ? 0.f : e.z;
        float mc = fmaxf(fmaxf(s3, s4), fmaxf(s5, s6));
        float m0 = fmaxf(fmaxf(mc, s0), fmaxf(s1, s2));
        float m1 = fmaxf(fmaxf(mc, s7), fmaxf(s1, s2));
        float m2 = fmaxf(fmaxf(mc, s2), fmaxf(s7, s8));
        float m3 = fmaxf(fmaxf(mc, s7), fmaxf(s8, s9));
        *(float4*)(tp + ly*SPITCH + x) = make_float4(m0, m1, m2, m3);
    }
}

// ---------------------------------------------------------------------------
// Fused NMS. One block per 64x64 tile, 1024 threads, 2 blocks/SM.
// H-pools quad-vectorized + flattened; passes restricted to the minimal
// regions their consumers need (backward dataflow shrink).
// ---------------------------------------------------------------------------
__global__ __launch_bounds__(NMS_THREADS, 2)
void k_nms(const float* __restrict__ bev,
           const float* __restrict__ raw,
           float* __restrict__ out) {
    extern __shared__ unsigned char smraw[];
    float* sbuf = (float*)smraw;
    float* tbuf = sbuf + BUF;
    unsigned int* mkw = (unsigned int*)(tbuf + BUF);  // max_mask bits
    unsigned int* hbw = mkw + RROWS*WPR;              // h-dilated bits
    unsigned int* spw = hbw + RROWS*WPR;              // supp (7x7 dil) bits
    float* sc = sbuf + GR*SPITCH + GC;
    float* tp = tbuf + GR*SPITCH + GC;

    const int tid  = threadIdx.x;
    const int wid  = tid >> 5;
    const int lane = tid & 31;
    const int b    = blockIdx.z;
    const int gx0  = blockIdx.x * TILE - HALO;
    const int gy0  = blockIdx.y * TILE - HALO;
    const float* g2 = bev + (b*7 + 2)*HW;
    const float* rw = raw + b*HW;

    // bit arrays init
    for (int i = tid; i < RROWS*WPR; i += NMS_THREADS) {
        mkw[i] = 0; hbw[i] = 0; spw[i] = 0;
    }

    // fused init+load over the FULL ring: gated score or -inf
    for (int r = wid; r < RROWS; r += NMS_NW) {
        int gy = gy0 + (r - GR);
        const float* rwr = rw + gy*WW;
        const float* g2r = g2 + gy*WW;
        bool rowin = (unsigned)gy < HH;
        for (int col = lane; col < SPITCH; col += 32) {
            int gx = gx0 + (col - GC);
            float v = -CUDART_INF_F;
            if (rowin && (unsigned)gx < WW)
                v = rwr[gx] * (g2r[gx] > 0.f ? 1.f : 0.f);
            sbuf[r*SPITCH + col] = v;
        }
    }
    __syncthreads();

    // P1: h 7-max sc -> tp, quads, all 94 rows
    for (int t = tid; t < 94*24; t += NMS_THREADS) {
        int ly = t / 24;
        int x  = (t % 24) << 2;
        const float* row = sc + ly*SPITCH;
        float4 a = *(const float4*)(row + x - 4);
        float4 c = *(const float4*)(row + x);
        float4 e = *(const float4*)(row + x + 4);
        float mc = fmaxf(fmaxf(c.x, c.y), fmaxf(c.z, c.w));
        float m0 = fmaxf(fmaxf(mc, a.y), fmaxf(a.z, a.w));
        float m1 = fmaxf(fmaxf(mc, e.x), fmaxf(a.z, a.w));
        float m2 = fmaxf(fmaxf(mc, a.w), fmaxf(e.x, e.y));
        float m3 = fmaxf(fmaxf(mc, e.x), fmaxf(e.y, e.z));
        *(float4*)(tp + ly*SPITCH + x) = make_float4(m0, m1, m2, m3);
    }
    __syncthreads();
    // P2: v 7-max of tp; mk bit = (max == sc) & in-image. Rows [3,91) only
    // (mk rows outside [6,94) are never consumed; zero-init stands in).
    for (int ly = 3 + wid; ly < 91; ly += NMS_NW) {
        for (int g = 0; g < 3; ++g) {
            int lx = g*32 + lane;
            bool pred = false;
            if (lx < LDIM) {
                const float* col = tp + ly*SPITCH + lx;
                float m = col[-3*SPITCH];
                #pragma unroll
                for (int k = -2; k <= 3; ++k) m = fmaxf(m, col[k*SPITCH]);
                float sv = sc[ly*SPITCH + lx];
                pred = (m == sv && sv >= 0.f);
            }
            unsigned bal = __ballot_sync(0xffffffffu, pred);
            if (lane == 0) mkw[(ly+GR)*WPR + 1 + g] = bal;
        }
    }
    __syncthreads();

    for (int it = 0; it < 2; ++it) {
        // P3: h-dilate mk bits (all word rows; cheap)
        for (int t = tid; t < 300; t += NMS_THREADS) {
            int row = t / 3, w = t % 3 + 1;
            const unsigned int* mr = mkw + row*WPR;
            unsigned a = mr[w-1], c = mr[w], d = mr[w+1];
            unsigned res = c;
            res |= __funnelshift_l(a, c, 1) | __funnelshift_r(c, d, 1);
            res |= __funnelshift_l(a, c, 2) | __funnelshift_r(c, d, 2);
            res |= __funnelshift_l(a, c, 3) | __funnelshift_r(c, d, 3);
            hbw[row*WPR + w] = res;
        }
        __syncthreads();
        // P4: v-dilate
        for (int t = tid; t < 282; t += NMS_THREADS) {
            int row = t / 3 + 3, w = t % 3 + 1;
            unsigned r = 0;
            #pragma unroll
            for (int k = -3; k <= 3; ++k) r |= hbw[(row+k)*WPR + w];
            spw[row*WPR + w] = r;
        }
        __syncthreads();
        // P5: h 7-max of (supbit ? 0 : sc) -> tp, quads, shrunk regions
        if (it == 0) p5_quads<6, 82, 0, 24>(sc, tp, spw, tid);
        else         p5_quads<12, 70, 3, 18>(sc, tp, spw, tid);
        __syncthreads();
        // P6: v 7-max of tp; cond = (!sup & sv>=0 & m==sv)
        //     it=0: mk |= cond over rows [9,85).  it=1: emit rows only.
        {
            int r0 = it ? HALO : 9;
            int r1 = it ? (HALO + TILE) : 85;
            for (int ly = r0 + wid; ly < r1; ly += NMS_NW) {
                const unsigned int* sr = spw + (ly+GR)*WPR + 1;
                unsigned int* mr = mkw + (ly+GR)*WPR + 1;
                for (int g = 0; g < 3; ++g) {
                    int lx = g*32 + lane;
                    bool cond = false;
                    float sv = 0.f;
                    unsigned oldw = mr[g];
                    if (lx < LDIM) {
                        const float* col = tp + ly*SPITCH + lx;
                        float m = col[-3*SPITCH];
                        #pragma unroll
                        for (int k = -2; k <= 3; ++k)
                            m = fmaxf(m, col[k*SPITCH]);
                        sv = sc[ly*SPITCH + lx];
                        unsigned supb = (sr[g] >> lane) & 1u;
                        cond = (!supb && sv >= 0.f && m == sv);
                    }
                    if (it == 0) {
                        unsigned bal = __ballot_sync(0xffffffffu, cond);
                        if (lane == 0 && bal) mr[g] |= bal;
                    } else {
                        bool c = false;
                        int gg = 0;
                        int ty = ly - HALO, tx = lx - HALO;
                        bool inter = ((unsigned)tx < TILE) && (lx < LDIM);
                        if (inter) {
                            bool fm = cond || (((oldw >> lane) & 1u) != 0u);
                            int gy = blockIdx.y*TILE + ty;
                            int gx = blockIdx.x*TILE + tx;
                            gg = gy*WW + gx;
                            out[OFF_SCORE + b*HW + gg] = sv;
                            c = fm && (sv > 0.f);
                            g_cmask[b*HW + gg] = c ? 1 : 0;
                        }
                        unsigned cb = __ballot_sync(0xffffffffu, c);
                        if (cb) {
                            int ldr = __ffs(cb) - 1;
                            int basep = 0;
                            if (lane == ldr)
                                basep = atomicAdd(&g_count[b], __popc(cb));
                            basep = __shfl_sync(0xffffffffu, basep, ldr);
                            if (c) {
                                int pos = basep +
                                          __popc(cb & ((1u << lane) - 1u));
                                if (pos < CAP) {
                                    unsigned long long key =
                                        ((unsigned long long)
                                         __float_as_uint(sv) << 32)
                                        | (unsigned int)(HW - 1 - gg);
                                    g_cand[b*CAP + pos] = key;
                                }
                            }
                        }
                    }
                }
            }
        }
        __syncthreads();
    }
}

// warp-aggregated histogram add (convergence-safe)
__device__ __forceinline__ void hist_add(unsigned int* h, unsigned bin,
                                         bool valid) {
    unsigned vm = __ballot_sync(0xffffffffu, valid);
    if (valid) {
        unsigned peers = __match_any_sync(vm, bin);
        int lane = threadIdx.x & 31;
        if (lane == __ffs(peers) - 1)
            atomicAdd(&h[bin], (unsigned)__popc(peers));
    }
}

// ---------------------------------------------------------------------------
// Merged threshold + select. One block per batch. NO writes to g_count here
// (reset happens in k_gather, strictly after all readers).
// ---------------------------------------------------------------------------
__global__ __launch_bounds__(1024)
void k_select() {
    __shared__ unsigned int h[4096];
    __shared__ unsigned int cs[1025];
    __shared__ unsigned long long sk[SURVCAP];
    __shared__ int sBin;
    __shared__ unsigned int sAbove;
    __shared__ unsigned long long sT;
    __shared__ int scnt;
    __shared__ int sn;

    const int b = blockIdx.x;
    const int tid = threadIdx.x;
    if (tid == 0) {
        sn = min(g_count[b], CAP);
        scnt = 0;
        sT = 0ULL;
    }
    __syncthreads();
    const int n = sn;
    const unsigned int target = (unsigned int)min(n, NKPT);
    const unsigned long long* base = g_cand + (size_t)b*CAP;

    if (target > 0) {
        const int nR = (n + 1023) & ~1023;

        // ---- level 1: bins = key bits [63:52] ----
        for (int i = tid; i < 4096; i += 1024) h[i] = 0;
        if (tid == 0) cs[1024] = 0;
        __syncthreads();
        for (int i = tid; i < nR; i += 1024) {
            bool valid = i < n;
            unsigned bin = valid ? (unsigned)(base[i] >> 52) : 0u;
            hist_add(h, bin, valid);
        }
        __syncthreads();
        unsigned h0 = h[4*tid], h1 = h[4*tid+1],
                 h2 = h[4*tid+2], h3 = h[4*tid+3];
        cs[tid] = h0 + h1 + h2 + h3;
        __syncthreads();
        for (int off = 1; off < 1024; off <<= 1) {
            unsigned v = cs[tid] + ((tid + off < 1024) ? cs[tid + off] : 0u);
            __syncthreads();
            cs[tid] = v;
            __syncthreads();
        }
        {
            unsigned s4 = cs[tid + 1];
            unsigned s3 = h3 + s4, s2 = h2 + s3, s1 = h1 + s2, s0 = h0 + s1;
            unsigned sf[5] = {s0, s1, s2, s3, s4};
            #pragma unroll
            for (int i = 0; i < 4; ++i)
                if (sf[i] >= target && sf[i+1] < target) {
                    sBin = 4*tid + i; sAbove = sf[i+1];
                }
        }
        __syncthreads();
        const unsigned long long B1 = (unsigned long long)sBin;
        const unsigned int rem = target - sAbove;   // >= 1

        // ---- level 2: bins = key bits [51:40], restricted to level-1 bin ----
        __syncthreads();
        for (int i = tid; i < 4096; i += 1024) h[i] = 0;
        __syncthreads();
        for (int i = tid; i < nR; i += 1024) {
            bool valid = false;
            unsigned bin = 0;
            if (i < n) {
                unsigned long long key = base[i];
                if ((key >> 52) == B1) {
                    valid = true;
                    bin = (unsigned)(key >> 40) & 0xFFFu;
                }
            }
            hist_add(h, bin, valid);
        }
        __syncthreads();
        h0 = h[4*tid]; h1 = h[4*tid+1]; h2 = h[4*tid+2]; h3 = h[4*tid+3];
        cs[tid] = h0 + h1 + h2 + h3;
        __syncthreads();
        for (int off = 1; off < 1024; off <<= 1) {
            unsigned v = cs[tid] + ((tid + off < 1024) ? cs[tid + off] : 0u);
            __syncthreads();
            cs[tid] = v;
            __syncthreads();
        }
        {
            unsigned s4 = cs[tid + 1];
            unsigned s3 = h3 + s4, s2 = h2 + s3, s1 = h1 + s2, s0 = h0 + s1;
            unsigned sf[5] = {s0, s1, s2, s3, s4};
            #pragma unroll
            for (int i = 0; i < 4; ++i)
                if (sf[i] >= rem && sf[i+1] < rem)
                    sT = (B1 << 52) | ((unsigned long long)(4*tid + i) << 40);
        }
        __syncthreads();

        // ---- Phase B: compact survivors, rank in smem ----
        const unsigned long long T = sT;
        for (int i = tid; i < n; i += 1024) {
            unsigned long long key = base[i];
            if (key >= T) {
                int p = atomicAdd(&scnt, 1);
                if (p < SURVCAP) sk[p] = key;
            }
        }
        __syncthreads();
        int m = scnt;

        if (m <= SURVCAP) {
            for (int i = tid; i < m; i += 1024) {
                unsigned long long key = sk[i];
                int r = 0;
                for (int j = 0; j < m; ++j) r += (sk[j] > key) ? 1 : 0;
                if (r < NKPT)
                    g_sel[b*NKPT + r] = HW - 1 - (int)(key & 0xffffffffu);
            }
        } else {
            // cold: exact rank via global scans, warp per survivor
            int lane = tid & 31, w = tid >> 5;
            for (int i = w; i < n; i += 32) {
                unsigned long long key = base[i];
                if (key < T) continue;
                int r = 0;
                for (int j = lane; j < n; j += 32)
                    r += (base[j] > key) ? 1 : 0;
                #pragma unroll
                for (int off = 16; off; off >>= 1)
                    r += __shfl_down_sync(0xffffffffu, r, off);
                if (lane == 0 && r < NKPT)
                    g_sel[b*NKPT + r] = HW - 1 - (int)(key & 0xffffffffu);
            }
        }
    }

    // cold: fewer than NKPT candidates -> ascending non-candidate indices
    if (n < NKPT) {
        __syncthreads();
        if (tid == 0) {
            int slot = n;
            for (int p = 0; p < HW && slot < NKPT; ++p)
                if (!g_cmask[b*HW + p]) g_sel[b*NKPT + (slot++)] = p;
        }
    }
}

// ---------------------------------------------------------------------------
// Gather: each thread handles 8 channels of one keypoint (MLP=8 scattered
// loads), stores coalesced along k. Groups 0..BB-1 also emit kpts+pixels.
// Resets g_count for the next graph replay (strictly after k_select).
// ---------------------------------------------------------------------------
__global__ __launch_bounds__(256)
void k_gather(const float* __restrict__ bev,
              const float* __restrict__ feat,
              float* __restrict__ out) {
    int t = blockIdx.x * blockDim.x + threadIdx.x;   // 32768 threads
    if (t < BB) g_count[t] = 0;
    int k   = t & (NKPT-1);
    int grp = t >> 9;            // (b, cq): 4 * 16
    int b   = grp >> 4;
    int cq  = grp & 15;
    int idx = g_sel[b*NKPT + k];

    if (grp < BB) {  // group 'grp' emits kpts+pixels for batch 'grp'
        int bk = grp;
        int idk = g_sel[bk*NKPT + k];
        int u = idk / WW, v = idk - u*WW;
        float4 kv = make_float4(bev[(bk*7 + 3)*HW + idk],
                                bev[(bk*7 + 4)*HW + idk], 0.f, 1.f);
        ((float4*)(out + OFF_KPTS))[bk*NKPT + k] = kv;
        ((float2*)(out + OFF_PIX))[bk*NKPT + k] =
            make_float2((float)u, (float)v);
    }

    const float* fb = feat + ((size_t)(b*NFEAT + cq*8))*HW + idx;
    float v0 = fb[0*HW];
    float v1 = fb[1*HW];
    float v2 = fb[2*HW];
    float v3 = fb[3*HW];
    float v4 = fb[4*HW];
    float v5 = fb[5*HW];
    float v6 = fb[6*HW];
    float v7 = fb[7*HW];
    float* ob = out + OFF_FEAS + (size_t)(b*NFEAT + cq*8)*NKPT + k;
    ob[0*NKPT] = v0;
    ob[1*NKPT] = v1;
    ob[2*NKPT] = v2;
    ob[3*NKPT] = v3;
    ob[4*NKPT] = v4;
    ob[5*NKPT] = v5;
    ob[6*NKPT] = v6;
    ob[7*NKPT] = v7;
}

extern "C" void kernel_launch(void* const* d_in, const int* in_sizes, int n_in,
                              void* d_out, int out_size) {
    const float* bev  = (const float*)d_in[0];
    const float* raw  = (const float*)d_in[1];
    const float* feat = (const float*)d_in[2];
    float* out = (float*)d_out;

    static bool attr_set = false;
    if (!attr_set) {
        cudaFuncSetAttribute(k_nms, cudaFuncAttributeMaxDynamicSharedMemorySize,
                             NMS_SMEM);
        attr_set = true;
    }

    dim3 ngrid(WW/TILE, HH/TILE, BB);   // 8 x 8 x 4
    k_nms<<<ngrid, NMS_THREADS, NMS_SMEM>>>(bev, raw, out);
    k_select<<<BB, 1024>>>();
    k_gather<<<128, 256>>>(bev, feat, out);
}

// round 13
// speedup vs baseline: 1.2169x; 1.0365x over previous
#include <cuda_runtime.h>
#include <math_constants.h>

#define BB 4
#define HH 512
#define WW 512
#define HW (HH*WW)
#define NKPT 512
#define CAP 65536
#define NFEAT 128

#define TILE 64
#define HALO 15
#define LDIM (TILE + 2*HALO)     // 94
#define GR 3                     // guard rows (top/bottom)
#define GC 4                     // guard cols left (16B alignment)
#define RROWS (LDIM + 2*GR)      // 100
#define SPITCH 104
#define BUF (RROWS*SPITCH)       // 10400
#define WPR 5                    // bit-words per row (slots 0,4 = zero guards)
#define NMS_SMEM (BUF*4*2 + RROWS*WPR*4*2)   // 2 float bufs + 2 bit arrays
#define NMS_THREADS 1024
#define NMS_NW (NMS_THREADS/32)

#define SURVCAP 3072

// Output layout (float32, reference tuple order)
#define OFF_SCORE 0
#define OFF_KPTS  (BB*HW)
#define OFF_FEAS  (OFF_KPTS + BB*NKPT*4)
#define OFF_PIX   (OFF_FEAS + BB*NFEAT*NKPT)

// Scratch
__device__ unsigned long long g_cand[BB*CAP];
__device__ unsigned char g_cmask[BB*HW];
__device__ int g_count[BB];
__device__ int g_sel[BB*NKPT];

// Fused 7x7 OR-dilation of mk bits -> sup bits (v-OR of 7 rows, then one
// h-dilate; commutes with the h-then-v order). One barrier instead of two.
template<int R0, int NR>
__device__ __forceinline__ void p34(const unsigned int* __restrict__ mkw,
                                    unsigned int* __restrict__ spw, int tid) {
    for (int t = tid; t < NR*3; t += NMS_THREADS) {
        int row = R0 + t / 3, w = t % 3 + 1;
        unsigned a = 0, c = 0, d = 0;
        #pragma unroll
        for (int k = -3; k <= 3; ++k) {
            const unsigned int* mr = mkw + (row+k)*WPR;
            a |= mr[w-1]; c |= mr[w]; d |= mr[w+1];
        }
        unsigned res = c;
        res |= __funnelshift_l(a, c, 1) | __funnelshift_r(c, d, 1);
        res |= __funnelshift_l(a, c, 2) | __funnelshift_r(c, d, 2);
        res |= __funnelshift_l(a, c, 3) | __funnelshift_r(c, d, 3);
        spw[row*WPR + w] = res;
    }
}

// quad h-pool of suppressed scores: compile-time region for magic-div
template<int R0, int NR, int Q0, int NQt>
__device__ __forceinline__ void p5_quads(const float* __restrict__ sc,
                                         float* __restrict__ tp,
                                         const unsigned int* __restrict__ spw,
                                         int tid) {
    for (int t = tid; t < NR*NQt; t += NMS_THREADS) {
        int ly = R0 + t / NQt;
        int x  = (Q0 + t % NQt) << 2;
        const float* row = sc + ly*SPITCH;
        const unsigned int* srG = spw + (ly+GR)*WPR;  // word0 = bits -32..-1
        int Bp = x + 29;                              // (x-3) + 32
        unsigned w0 = srG[Bp >> 5];
        unsigned w1 = srG[(Bp >> 5) + 1];
        unsigned win = __funnelshift_r(w0, w1, Bp);
        float4 a = *(const float4*)(row + x - 4);
        float4 c = *(const float4*)(row + x);
        float4 e = *(const float4*)(row + x + 4);
        float s0 = (win & 1u)    ? 0.f : a.y;
        float s1 = (win & 2u)    ? 0.f : a.z;
        float s2 = (win & 4u)    ? 0.f : a.w;
        float s3 = (win & 8u)    ? 0.f : c.x;
        float s4 = (win & 16u)   ? 0.f : c.y;
        float s5 = (win & 32u)   ? 0.f : c.z;
        float s6 = (win & 64u)   ? 0.f : c.w;
        float s7 = (win & 128u)  ? 0.f : e.x;
        float s8 = (win & 256u)  ? 0.f : e.y;
        float s9 = (win & 512u)  ? 0.f : e.z;
        float mc = fmaxf(fmaxf(s3, s4), fmaxf(s5, s6));
        float m0 = fmaxf(fmaxf(mc, s0), fmaxf(s1, s2));
        float m1 = fmaxf(fmaxf(mc, s7), fmaxf(s1, s2));
        float m2 = fmaxf(fmaxf(mc, s2), fmaxf(s7, s8));
        float m3 = fmaxf(fmaxf(mc, s7), fmaxf(s8, s9));
        *(float4*)(tp + ly*SPITCH + x) = make_float4(m0, m1, m2, m3);
    }
}

// ---------------------------------------------------------------------------
// Fused NMS. One block per 64x64 tile, 1024 threads, 2 blocks/SM. 9 barriers.
// ---------------------------------------------------------------------------
__global__ __launch_bounds__(NMS_THREADS, 2)
void k_nms(const float* __restrict__ bev,
           const float* __restrict__ raw,
           float* __restrict__ out) {
    extern __shared__ unsigned char smraw[];
    float* sbuf = (float*)smraw;
    float* tbuf = sbuf + BUF;
    unsigned int* mkw = (unsigned int*)(tbuf + BUF);  // max_mask bits
    unsigned int* spw = mkw + RROWS*WPR;              // supp (7x7 dil) bits
    float* sc = sbuf + GR*SPITCH + GC;
    float* tp = tbuf + GR*SPITCH + GC;

    const int tid  = threadIdx.x;
    const int wid  = tid >> 5;
    const int lane = tid & 31;
    const int b    = blockIdx.z;
    const int gx0  = blockIdx.x * TILE - HALO;
    const int gy0  = blockIdx.y * TILE - HALO;
    const float* g2 = bev + (b*7 + 2)*HW;
    const float* rw = raw + b*HW;

    // bit arrays init (guard words/rows stay zero forever)
    for (int i = tid; i < RROWS*WPR; i += NMS_THREADS) {
        mkw[i] = 0; spw[i] = 0;
    }

    // fused init+load over the FULL ring: gated score or -inf
    for (int r = wid; r < RROWS; r += NMS_NW) {
        int gy = gy0 + (r - GR);
        const float* rwr = rw + gy*WW;
        const float* g2r = g2 + gy*WW;
        bool rowin = (unsigned)gy < HH;
        for (int col = lane; col < SPITCH; col += 32) {
            int gx = gx0 + (col - GC);
            float v = -CUDART_INF_F;
            if (rowin && (unsigned)gx < WW)
                v = rwr[gx] * (g2r[gx] > 0.f ? 1.f : 0.f);
            sbuf[r*SPITCH + col] = v;
        }
    }
    __syncthreads();

    // P1: h 7-max sc -> tp, quads, all 94 rows
    for (int t = tid; t < 94*24; t += NMS_THREADS) {
        int ly = t / 24;
        int x  = (t % 24) << 2;
        const float* row = sc + ly*SPITCH;
        float4 a = *(const float4*)(row + x - 4);
        float4 c = *(const float4*)(row + x);
        float4 e = *(const float4*)(row + x + 4);
        float mc = fmaxf(fmaxf(c.x, c.y), fmaxf(c.z, c.w));
        float m0 = fmaxf(fmaxf(mc, a.y), fmaxf(a.z, a.w));
        float m1 = fmaxf(fmaxf(mc, e.x), fmaxf(a.z, a.w));
        float m2 = fmaxf(fmaxf(mc, a.w), fmaxf(e.x, e.y));
        float m3 = fmaxf(fmaxf(mc, e.x), fmaxf(e.y, e.z));
        *(float4*)(tp + ly*SPITCH + x) = make_float4(m0, m1, m2, m3);
    }
    __syncthreads();
    // P2: v 7-max of tp; mk bit = (max == sc) & in-image. Rows [3,91) only.
    for (int ly = 3 + wid; ly < 91; ly += NMS_NW) {
        for (int g = 0; g < 3; ++g) {
            int lx = g*32 + lane;
            bool pred = false;
            if (lx < LDIM) {
                const float* col = tp + ly*SPITCH + lx;
                float m = col[-3*SPITCH];
                #pragma unroll
                for (int k = -2; k <= 3; ++k) m = fmaxf(m, col[k*SPITCH]);
                float sv = sc[ly*SPITCH + lx];
                pred = (m == sv && sv >= 0.f);
            }
            unsigned bal = __ballot_sync(0xffffffffu, pred);
            if (lane == 0) mkw[(ly+GR)*WPR + 1 + g] = bal;
        }
    }
    __syncthreads();

    for (int it = 0; it < 2; ++it) {
        // P34: fused 7x7 dilation mk -> sup, shrunk regions
        if (it == 0) p34<9, 82>(mkw, spw, tid);
        else         p34<15, 70>(mkw, spw, tid);
        __syncthreads();
        // P5: h 7-max of (supbit ? 0 : sc) -> tp, quads, shrunk regions
        if (it == 0) p5_quads<6, 82, 0, 24>(sc, tp, spw, tid);
        else         p5_quads<12, 70, 3, 18>(sc, tp, spw, tid);
        __syncthreads();
        // P6: v 7-max of tp; cond = (!sup & sv>=0 & m==sv)
        //     it=0: mk |= cond over rows [9,85).  it=1: emit rows only.
        {
            int r0 = it ? HALO : 9;
            int r1 = it ? (HALO + TILE) : 85;
            for (int ly = r0 + wid; ly < r1; ly += NMS_NW) {
                const unsigned int* sr = spw + (ly+GR)*WPR + 1;
                unsigned int* mr = mkw + (ly+GR)*WPR + 1;
                for (int g = 0; g < 3; ++g) {
                    int lx = g*32 + lane;
                    bool cond = false;
                    float sv = 0.f;
                    unsigned oldw = mr[g];
                    if (lx < LDIM) {
                        const float* col = tp + ly*SPITCH + lx;
                        float m = col[-3*SPITCH];
                        #pragma unroll
                        for (int k = -2; k <= 3; ++k)
                            m = fmaxf(m, col[k*SPITCH]);
                        sv = sc[ly*SPITCH + lx];
                        unsigned supb = (sr[g] >> lane) & 1u;
                        cond = (!supb && sv >= 0.f && m == sv);
                    }
                    if (it == 0) {
                        unsigned bal = __ballot_sync(0xffffffffu, cond);
                        if (lane == 0 && bal) mr[g] |= bal;
                    } else {
                        bool c = false;
                        int gg = 0;
                        int ty = ly - HALO, tx = lx - HALO;
                        bool inter = ((unsigned)tx < TILE) && (lx < LDIM);
                        if (inter) {
                            bool fm = cond || (((oldw >> lane) & 1u) != 0u);
                            int gy = blockIdx.y*TILE + ty;
                            int gx = blockIdx.x*TILE + tx;
                            gg = gy*WW + gx;
                            out[OFF_SCORE + b*HW + gg] = sv;
                            c = fm && (sv > 0.f);
                            g_cmask[b*HW + gg] = c ? 1 : 0;
                        }
                        unsigned cb = __ballot_sync(0xffffffffu, c);
                        if (cb) {
                            int ldr = __ffs(cb) - 1;
                            int basep = 0;
                            if (lane == ldr)
                                basep = atomicAdd(&g_count[b], __popc(cb));
                            basep = __shfl_sync(0xffffffffu, basep, ldr);
                            if (c) {
                                int pos = basep +
                                          __popc(cb & ((1u << lane) - 1u));
                                if (pos < CAP) {
                                    unsigned long long key =
                                        ((unsigned long long)
                                         __float_as_uint(sv) << 32)
                                        | (unsigned int)(HW - 1 - gg);
                                    g_cand[b*CAP + pos] = key;
                                }
                            }
                        }
                    }
                }
            }
        }
        __syncthreads();
    }
}

// warp-aggregated histogram add (convergence-safe)
__device__ __forceinline__ void hist_add(unsigned int* h, unsigned bin,
                                         bool valid) {
    unsigned vm = __ballot_sync(0xffffffffu, valid);
    if (valid) {
        unsigned peers = __match_any_sync(vm, bin);
        int lane = threadIdx.x & 31;
        if (lane == __ffs(peers) - 1)
            atomicAdd(&h[bin], (unsigned)__popc(peers));
    }
}

// Inclusive suffix scan (chunk granularity) across 1024 threads; 2 barriers.
// wtot must hold >= 32 unsigned. Returns sum of chunks of all tid' >= tid.
__device__ __forceinline__ unsigned suffix_scan(unsigned chunk,
                                                unsigned* wtot, int tid) {
    int lane = tid & 31, wd = tid >> 5;
    unsigned v = chunk;
    #pragma unroll
    for (int off = 1; off < 32; off <<= 1) {
        unsigned o = __shfl_down_sync(0xffffffffu, v, off);
        if (lane + off < 32) v += o;
    }
    if (lane == 0) wtot[wd] = v;      // warp total (lane0 suffix = all)
    __syncthreads();
    if (wd == 0) {
        unsigned t = wtot[lane];
        unsigned s = t;
        #pragma unroll
        for (int off = 1; off < 32; off <<= 1) {
            unsigned o = __shfl_down_sync(0xffffffffu, s, off);
            if (lane + off < 32) s += o;
        }
        wtot[lane] = s - t;           // exclusive suffix over later warps
    }
    __syncthreads();
    return v + wtot[wd];
}

// ---------------------------------------------------------------------------
// Merged threshold + select. One block per batch. NO writes to g_count here.
// ---------------------------------------------------------------------------
__global__ __launch_bounds__(1024)
void k_select() {
    __shared__ unsigned int h[4096];
    __shared__ unsigned int wtot[32];
    __shared__ unsigned long long sk[SURVCAP];
    __shared__ int sBin;
    __shared__ unsigned int sAbove;
    __shared__ unsigned long long sT;
    __shared__ int scnt;
    __shared__ int sn;

    const int b = blockIdx.x;
    const int tid = threadIdx.x;
    if (tid == 0) {
        sn = min(g_count[b], CAP);
        scnt = 0;
        sT = 0ULL;
    }
    __syncthreads();
    const int n = sn;
    const unsigned int target = (unsigned int)min(n, NKPT);
    const unsigned long long* base = g_cand + (size_t)b*CAP;

    if (target > 0) {
        const int nR = (n + 1023) & ~1023;

        // ---- level 1: bins = key bits [63:52] ----
        for (int i = tid; i < 4096; i += 1024) h[i] = 0;
        __syncthreads();
        for (int i = tid; i < nR; i += 1024) {
            bool valid = i < n;
            unsigned bin = valid ? (unsigned)(base[i] >> 52) : 0u;
            hist_add(h, bin, valid);
        }
        __syncthreads();
        unsigned h0 = h[4*tid], h1 = h[4*tid+1],
                 h2 = h[4*tid+2], h3 = h[4*tid+3];
        unsigned chunk = h0 + h1 + h2 + h3;
        unsigned S = suffix_scan(chunk, wtot, tid);
        {
            unsigned s4 = S - chunk;
            unsigned s3 = h3 + s4, s2 = h2 + s3, s1 = h1 + s2, s0 = h0 + s1;
            unsigned sf[5] = {s0, s1, s2, s3, s4};
            #pragma unroll
            for (int i = 0; i < 4; ++i)
                if (sf[i] >= target && sf[i+1] < target) {
                    sBin = 4*tid + i; sAbove = sf[i+1];
                }
        }
        __syncthreads();
        const unsigned long long B1 = (unsigned long long)sBin;
        const unsigned int rem = target - sAbove;   // >= 1

        // ---- level 2: bins = key bits [51:40], restricted to level-1 bin ----
        for (int i = tid; i < 4096; i += 1024) h[i] = 0;
        __syncthreads();
        for (int i = tid; i < nR; i += 1024) {
            bool valid = false;
            unsigned bin = 0;
            if (i < n) {
                unsigned long long key = base[i];
                if ((key >> 52) == B1) {
                    valid = true;
                    bin = (unsigned)(key >> 40) & 0xFFFu;
                }
            }
            hist_add(h, bin, valid);
        }
        __syncthreads();
        h0 = h[4*tid]; h1 = h[4*tid+1]; h2 = h[4*tid+2]; h3 = h[4*tid+3];
        chunk = h0 + h1 + h2 + h3;
        S = suffix_scan(chunk, wtot, tid);
        {
            unsigned s4 = S - chunk;
            unsigned s3 = h3 + s4, s2 = h2 + s3, s1 = h1 + s2, s0 = h0 + s1;
            unsigned sf[5] = {s0, s1, s2, s3, s4};
            #pragma unroll
            for (int i = 0; i < 4; ++i)
                if (sf[i] >= rem && sf[i+1] < rem)
                    sT = (B1 << 52) | ((unsigned long long)(4*tid + i) << 40);
        }
        __syncthreads();

        // ---- Phase B: compact survivors, rank in smem ----
        const unsigned long long T = sT;
        for (int i = tid; i < n; i += 1024) {
            unsigned long long key = base[i];
            if (key >= T) {
                int p = atomicAdd(&scnt, 1);
                if (p < SURVCAP) sk[p] = key;
            }
        }
        __syncthreads();
        int m = scnt;

        if (m <= SURVCAP) {
            for (int i = tid; i < m; i += 1024) {
                unsigned long long key = sk[i];
                int r = 0;
                for (int j = 0; j < m; ++j) r += (sk[j] > key) ? 1 : 0;
                if (r < NKPT)
                    g_sel[b*NKPT + r] = HW - 1 - (int)(key & 0xffffffffu);
            }
        } else {
            // cold: exact rank via global scans, warp per survivor
            int lane = tid & 31, w = tid >> 5;
            for (int i = w; i < n; i += 32) {
                unsigned long long key = base[i];
                if (key < T) continue;
                int r = 0;
                for (int j = lane; j < n; j += 32)
                    r += (base[j] > key) ? 1 : 0;
                #pragma unroll
                for (int off = 16; off; off >>= 1)
                    r += __shfl_down_sync(0xffffffffu, r, off);
                if (lane == 0 && r < NKPT)
                    g_sel[b*NKPT + r] = HW - 1 - (int)(key & 0xffffffffu);
            }
        }
    }

    // cold: fewer than NKPT candidates -> ascending non-candidate indices
    if (n < NKPT) {
        __syncthreads();
        if (tid == 0) {
            int slot = n;
            for (int p = 0; p < HW && slot < NKPT; ++p)
                if (!g_cmask[b*HW + p]) g_sel[b*NKPT + (slot++)] = p;
        }
    }
}

// ---------------------------------------------------------------------------
// Gather: each thread handles 8 channels of one keypoint (MLP=8 scattered
// loads), stores coalesced along k. Groups 0..BB-1 also emit kpts+pixels.
// Resets g_count for the next graph replay (strictly after k_select).
// ---------------------------------------------------------------------------
__global__ __launch_bounds__(256)
void k_gather(const float* __restrict__ bev,
              const float* __restrict__ feat,
              float* __restrict__ out) {
    int t = blockIdx.x * blockDim.x + threadIdx.x;   // 32768 threads
    if (t < BB) g_count[t] = 0;
    int k   = t & (NKPT-1);
    int grp = t >> 9;            // (b, cq): 4 * 16
    int b   = grp >> 4;
    int cq  = grp & 15;
    int idx = g_sel[b*NKPT + k];

    if (grp < BB) {  // group 'grp' emits kpts+pixels for batch 'grp'
        int bk = grp;
        int idk = g_sel[bk*NKPT + k];
        int u = idk / WW, v = idk - u*WW;
        float4 kv = make_float4(bev[(bk*7 + 3)*HW + idk],
                                bev[(bk*7 + 4)*HW + idk], 0.f, 1.f);
        ((float4*)(out + OFF_KPTS))[bk*NKPT + k] = kv;
        ((float2*)(out + OFF_PIX))[bk*NKPT + k] =
            make_float2((float)u, (float)v);
    }

    const float* fb = feat + ((size_t)(b*NFEAT + cq*8))*HW + idx;
    float v0 = fb[0*HW];
    float v1 = fb[1*HW];
    float v2 = fb[2*HW];
    float v3 = fb[3*HW];
    float v4 = fb[4*HW];
    float v5 = fb[5*HW];
    float v6 = fb[6*HW];
    float v7 = fb[7*HW];
    float* ob = out + OFF_FEAS + (size_t)(b*NFEAT + cq*8)*NKPT + k;
    ob[0*NKPT] = v0;
    ob[1*NKPT] = v1;
    ob[2*NKPT] = v2;
    ob[3*NKPT] = v3;
    ob[4*NKPT] = v4;
    ob[5*NKPT] = v5;
    ob[6*NKPT] = v6;
    ob[7*NKPT] = v7;
}

extern "C" void kernel_launch(void* const* d_in, const int* in_sizes, int n_in,
                              void* d_out, int out_size) {
    const float* bev  = (const float*)d_in[0];
    const float* raw  = (const float*)d_in[1];
    const float* feat = (const float*)d_in[2];
    float* out = (float*)d_out;

    static bool attr_set = false;
    if (!attr_set) {
        cudaFuncSetAttribute(k_nms, cudaFuncAttributeMaxDynamicSharedMemorySize,
                             NMS_SMEM);
        attr_set = true;
    }

    dim3 ngrid(WW/TILE, HH/TILE, BB);   // 8 x 8 x 4
    k_nms<<<ngrid, NMS_THREADS, NMS_SMEM>>>(bev, raw, out);
    k_select<<<BB, 1024>>>();
    k_gather<<<128, 256>>>(bev, feat, out);
}

// round 14
// speedup vs baseline: 1.4178x; 1.1651x over previous
#include <cuda_runtime.h>
#include <math_constants.h>

#define BB 4
#define HH 512
#define WW 512
#define HW (HH*WW)
#define NKPT 512
#define CAP 65536
#define NFEAT 128

#define TILE 64
#define HALO 15
#define LDIM (TILE + 2*HALO)     // 94
#define GR 3                     // guard rows (top/bottom)
#define GC 4                     // guard cols left (16B alignment)
#define RROWS (LDIM + 2*GR)      // 100
#define SPITCH 104
#define BUF (RROWS*SPITCH)       // 10400
#define WPR 5                    // bit-words per row (slots 0,4 = zero guards)
#define NMS_SMEM (BUF*4*2 + RROWS*WPR*4*2)   // 2 float bufs + 2 bit arrays
#define NMS_THREADS 1024
#define NMS_NW (NMS_THREADS/32)

#define SURVCAP 3072

// Output layout (float32, reference tuple order)
#define OFF_SCORE 0
#define OFF_KPTS  (BB*HW)
#define OFF_FEAS  (OFF_KPTS + BB*NKPT*4)
#define OFF_PIX   (OFF_FEAS + BB*NFEAT*NKPT)

// Scratch
__device__ unsigned long long g_cand[BB*CAP];
__device__ unsigned char g_cmask[BB*HW];
__device__ int g_count[BB];
__device__ int g_sel[BB*NKPT];

// Fused 7x7 OR-dilation of mk bits -> sup bits
template<int R0, int NR>
__device__ __forceinline__ void p34(const unsigned int* __restrict__ mkw,
                                    unsigned int* __restrict__ spw, int tid) {
    for (int t = tid; t < NR*3; t += NMS_THREADS) {
        int row = R0 + t / 3, w = t % 3 + 1;
        unsigned a = 0, c = 0, d = 0;
        #pragma unroll
        for (int k = -3; k <= 3; ++k) {
            const unsigned int* mr = mkw + (row+k)*WPR;
            a |= mr[w-1]; c |= mr[w]; d |= mr[w+1];
        }
        unsigned res = c;
        res |= __funnelshift_l(a, c, 1) | __funnelshift_r(c, d, 1);
        res |= __funnelshift_l(a, c, 2) | __funnelshift_r(c, d, 2);
        res |= __funnelshift_l(a, c, 3) | __funnelshift_r(c, d, 3);
        spw[row*WPR + w] = res;
    }
}

// quad h-pool of suppressed scores
template<int R0, int NR, int Q0, int NQt>
__device__ __forceinline__ void p5_quads(const float* __restrict__ sc,
                                         float* __restrict__ tp,
                                         const unsigned int* __restrict__ spw,
                                         int tid) {
    for (int t = tid; t < NR*NQt; t += NMS_THREADS) {
        int ly = R0 + t / NQt;
        int x  = (Q0 + t % NQt) << 2;
        const float* row = sc + ly*SPITCH;
        const unsigned int* srG = spw + (ly+GR)*WPR;  // word0 = bits -32..-1
        int Bp = x + 29;                              // (x-3) + 32
        unsigned w0 = srG[Bp >> 5];
        unsigned w1 = srG[(Bp >> 5) + 1];
        unsigned win = __funnelshift_r(w0, w1, Bp);
        float4 a = *(const float4*)(row + x - 4);
        float4 c = *(const float4*)(row + x);
        float4 e = *(const float4*)(row + x + 4);
        float s0 = (win & 1u)    ? 0.f : a.y;
        float s1 = (win & 2u)    ? 0.f : a.z;
        float s2 = (win & 4u)    ? 0.f : a.w;
        float s3 = (win & 8u)    ? 0.f : c.x;
        float s4 = (win & 16u)   ? 0.f : c.y;
        float s5 = (win & 32u)   ? 0.f : c.z;
        float s6 = (win & 64u)   ? 0.f : c.w;
        float s7 = (win & 128u)  ? 0.f : e.x;
        float s8 = (win & 256u)  ? 0.f : e.y;
        float s9 = (win & 512u)  ? 0.f : e.z;
        float mc = fmaxf(fmaxf(s3, s4), fmaxf(s5, s6));
        float m0 = fmaxf(fmaxf(mc, s0), fmaxf(s1, s2));
        float m1 = fmaxf(fmaxf(mc, s7), fmaxf(s1, s2));
        float m2 = fmaxf(fmaxf(mc, s2), fmaxf(s7, s8));
        float m3 = fmaxf(fmaxf(mc, s7), fmaxf(s8, s9));
        *(float4*)(tp + ly*SPITCH + x) = make_float4(m0, m1, m2, m3);
    }
}

// ---------------------------------------------------------------------------
// Fused NMS. One block per 64x64 tile, 1024 threads, 2 blocks/SM.
// ---------------------------------------------------------------------------
__global__ __launch_bounds__(NMS_THREADS, 2)
void k_nms(const float* __restrict__ bev,
           const float* __restrict__ raw,
           float* __restrict__ out) {
    extern __shared__ unsigned char smraw[];
    float* sbuf = (float*)smraw;
    float* tbuf = sbuf + BUF;
    unsigned int* mkw = (unsigned int*)(tbuf + BUF);  // max_mask bits
    unsigned int* spw = mkw + RROWS*WPR;              // supp (7x7 dil) bits
    float* sc = sbuf + GR*SPITCH + GC;
    float* tp = tbuf + GR*SPITCH + GC;

    const int tid  = threadIdx.x;
    const int wid  = tid >> 5;
    const int lane = tid & 31;
    const int b    = blockIdx.z;
    const int gx0  = blockIdx.x * TILE - HALO;
    const int gy0  = blockIdx.y * TILE - HALO;
    const float* g2 = bev + (b*7 + 2)*HW;
    const float* rw = raw + b*HW;

    // bit arrays init (guard words/rows stay zero forever)
    for (int i = tid; i < RROWS*WPR; i += NMS_THREADS) {
        mkw[i] = 0; spw[i] = 0;
    }

    // fused init+load over the FULL ring: gated score or -inf
    for (int r = wid; r < RROWS; r += NMS_NW) {
        int gy = gy0 + (r - GR);
        const float* rwr = rw + gy*WW;
        const float* g2r = g2 + gy*WW;
        bool rowin = (unsigned)gy < HH;
        for (int col = lane; col < SPITCH; col += 32) {
            int gx = gx0 + (col - GC);
            float v = -CUDART_INF_F;
            if (rowin && (unsigned)gx < WW)
                v = rwr[gx] * (g2r[gx] > 0.f ? 1.f : 0.f);
            sbuf[r*SPITCH + col] = v;
        }
    }
    __syncthreads();

    // P1: h 7-max sc -> tp, quads, all 94 rows
    for (int t = tid; t < 94*24; t += NMS_THREADS) {
        int ly = t / 24;
        int x  = (t % 24) << 2;
        const float* row = sc + ly*SPITCH;
        float4 a = *(const float4*)(row + x - 4);
        float4 c = *(const float4*)(row + x);
        float4 e = *(const float4*)(row + x + 4);
        float mc = fmaxf(fmaxf(c.x, c.y), fmaxf(c.z, c.w));
        float m0 = fmaxf(fmaxf(mc, a.y), fmaxf(a.z, a.w));
        float m1 = fmaxf(fmaxf(mc, e.x), fmaxf(a.z, a.w));
        float m2 = fmaxf(fmaxf(mc, a.w), fmaxf(e.x, e.y));
        float m3 = fmaxf(fmaxf(mc, e.x), fmaxf(e.y, e.z));
        *(float4*)(tp + ly*SPITCH + x) = make_float4(m0, m1, m2, m3);
    }
    __syncthreads();
    // P2: v 7-max of tp; mk bit = (max == sc) & in-image. Rows [3,91) only.
    for (int ly = 3 + wid; ly < 91; ly += NMS_NW) {
        for (int g = 0; g < 3; ++g) {
            int lx = g*32 + lane;
            bool pred = false;
            if (lx < LDIM) {
                const float* col = tp + ly*SPITCH + lx;
                float m = col[-3*SPITCH];
                #pragma unroll
                for (int k = -2; k <= 3; ++k) m = fmaxf(m, col[k*SPITCH]);
                float sv = sc[ly*SPITCH + lx];
                pred = (m == sv && sv >= 0.f);
            }
            unsigned bal = __ballot_sync(0xffffffffu, pred);
            if (lane == 0) mkw[(ly+GR)*WPR + 1 + g] = bal;
        }
    }
    __syncthreads();

    // ---- iteration 0 ----
    p34<9, 82>(mkw, spw, tid);
    __syncthreads();
    p5_quads<6, 82, 0, 24>(sc, tp, spw, tid);
    __syncthreads();
    // P6 it0: mk |= (!sup & sv>=0 & m==sv) over rows [9,85), full width
    for (int ly = 9 + wid; ly < 85; ly += NMS_NW) {
        const unsigned int* sr = spw + (ly+GR)*WPR + 1;
        unsigned int* mr = mkw + (ly+GR)*WPR + 1;
        for (int g = 0; g < 3; ++g) {
            int lx = g*32 + lane;
            bool cond = false;
            if (lx < LDIM) {
                const float* col = tp + ly*SPITCH + lx;
                float m = col[-3*SPITCH];
                #pragma unroll
                for (int k = -2; k <= 3; ++k) m = fmaxf(m, col[k*SPITCH]);
                float sv = sc[ly*SPITCH + lx];
                unsigned supb = (sr[g] >> lane) & 1u;
                cond = (!supb && sv >= 0.f && m == sv);
            }
            unsigned bal = __ballot_sync(0xffffffffu, cond);
            if (lane == 0 && bal) mr[g] |= bal;
        }
    }
    __syncthreads();

    // ---- iteration 1 ----
    p34<15, 70>(mkw, spw, tid);
    __syncthreads();
    p5_quads<12, 70, 3, 18>(sc, tp, spw, tid);
    __syncthreads();
    // P6 it1 (emit): interior columns only (2 groups of 32), warp = 2 rows,
    // ONE aggregated atomic per row per warp.
    {
        int ly0 = HALO + (wid << 1);
        #pragma unroll
        for (int r = 0; r < 2; ++r) {
            int ly = ly0 + r;
            const unsigned int* sr = spw + (ly+GR)*WPR + 1;
            const unsigned int* mr = mkw + (ly+GR)*WPR + 1;
            unsigned cb[2];
            float svv[2];
            #pragma unroll
            for (int g = 0; g < 2; ++g) {
                int lx = HALO + g*32 + lane;
                const float* col = tp + ly*SPITCH + lx;
                float m = col[-3*SPITCH];
                #pragma unroll
                for (int k = -2; k <= 3; ++k) m = fmaxf(m, col[k*SPITCH]);
                float sv = sc[ly*SPITCH + lx];
                unsigned supb = (sr[lx >> 5] >> (lx & 31)) & 1u;
                bool cond = (!supb && sv >= 0.f && m == sv);
                bool fm = cond || ((mr[lx >> 5] >> (lx & 31)) & 1u);
                int gg = (blockIdx.y*TILE + ly - HALO)*WW
                         + blockIdx.x*TILE + lx - HALO;
                out[OFF_SCORE + b*HW + gg] = sv;
                bool c = fm && (sv > 0.f);
                g_cmask[b*HW + gg] = c ? 1 : 0;
                cb[g] = __ballot_sync(0xffffffffu, c);
                svv[g] = sv;
            }
            int total = __popc(cb[0]) + __popc(cb[1]);
            int basep = 0;
            if (lane == 0 && total) basep = atomicAdd(&g_count[b], total);
            basep = __shfl_sync(0xffffffffu, basep, 0);
            #pragma unroll
            for (int g = 0; g < 2; ++g) {
                if ((cb[g] >> lane) & 1u) {
                    int pos = basep + __popc(cb[g] & ((1u << lane) - 1u));
                    if (pos < CAP) {
                        int gg = (blockIdx.y*TILE + ly - HALO)*WW
                                 + blockIdx.x*TILE + HALO + g*32 + lane - HALO;
                        unsigned long long key =
                            ((unsigned long long)__float_as_uint(svv[g]) << 32)
                            | (unsigned int)(HW - 1 - gg);
                        g_cand[b*CAP + pos] = key;
                    }
                }
                basep += __popc(cb[g]);
            }
        }
    }
}

// warp-aggregated histogram add (convergence-safe)
__device__ __forceinline__ void hist_add(unsigned int* h, unsigned bin,
                                         bool valid) {
    unsigned vm = __ballot_sync(0xffffffffu, valid);
    if (valid) {
        unsigned peers = __match_any_sync(vm, bin);
        int lane = threadIdx.x & 31;
        if (lane == __ffs(peers) - 1)
            atomicAdd(&h[bin], (unsigned)__popc(peers));
    }
}

// Inclusive suffix scan (chunk granularity) across 1024 threads; 2 barriers.
__device__ __forceinline__ unsigned suffix_scan(unsigned chunk,
                                                unsigned* wtot, int tid) {
    int lane = tid & 31, wd = tid >> 5;
    unsigned v = chunk;
    #pragma unroll
    for (int off = 1; off < 32; off <<= 1) {
        unsigned o = __shfl_down_sync(0xffffffffu, v, off);
        if (lane + off < 32) v += o;
    }
    if (lane == 0) wtot[wd] = v;
    __syncthreads();
    if (wd == 0) {
        unsigned t = wtot[lane];
        unsigned s = t;
        #pragma unroll
        for (int off = 1; off < 32; off <<= 1) {
            unsigned o = __shfl_down_sync(0xffffffffu, s, off);
            if (lane + off < 32) s += o;
        }
        wtot[lane] = s - t;
    }
    __syncthreads();
    return v + wtot[wd];
}

// ---------------------------------------------------------------------------
// Merged threshold + select. One block per batch. NO writes to g_count here.
// ---------------------------------------------------------------------------
__global__ __launch_bounds__(1024)
void k_select() {
    __shared__ unsigned int h[4096];
    __shared__ unsigned int wtot[32];
    __shared__ unsigned long long sk[SURVCAP];
    __shared__ int sBin;
    __shared__ unsigned int sAbove;
    __shared__ unsigned long long sT;
    __shared__ int scnt;
    __shared__ int sn;

    const int b = blockIdx.x;
    const int tid = threadIdx.x;
    if (tid == 0) {
        sn = min(g_count[b], CAP);
        scnt = 0;
        sT = 0ULL;
    }
    __syncthreads();
    const int n = sn;
    const unsigned int target = (unsigned int)min(n, NKPT);
    const unsigned long long* base = g_cand + (size_t)b*CAP;

    if (target > 0) {
        const int nR = (n + 1023) & ~1023;

        // ---- level 1: bins = key bits [63:52] ----
        for (int i = tid; i < 4096; i += 1024) h[i] = 0;
        __syncthreads();
        for (int i = tid; i < nR; i += 1024) {
            bool valid = i < n;
            unsigned bin = valid ? (unsigned)(base[i] >> 52) : 0u;
            hist_add(h, bin, valid);
        }
        __syncthreads();
        unsigned h0 = h[4*tid], h1 = h[4*tid+1],
                 h2 = h[4*tid+2], h3 = h[4*tid+3];
        unsigned chunk = h0 + h1 + h2 + h3;
        unsigned S = suffix_scan(chunk, wtot, tid);
        {
            unsigned s4 = S - chunk;
            unsigned s3 = h3 + s4, s2 = h2 + s3, s1 = h1 + s2, s0 = h0 + s1;
            unsigned sf[5] = {s0, s1, s2, s3, s4};
            #pragma unroll
            for (int i = 0; i < 4; ++i)
                if (sf[i] >= target && sf[i+1] < target) {
                    sBin = 4*tid + i; sAbove = sf[i+1];
                }
        }
        __syncthreads();
        const unsigned long long B1 = (unsigned long long)sBin;
        const unsigned int rem = target - sAbove;   // >= 1

        // ---- level 2: bins = key bits [51:40], restricted to level-1 bin ----
        for (int i = tid; i < 4096; i += 1024) h[i] = 0;
        __syncthreads();
        for (int i = tid; i < nR; i += 1024) {
            bool valid = false;
            unsigned bin = 0;
            if (i < n) {
                unsigned long long key = base[i];
                if ((key >> 52) == B1) {
                    valid = true;
                    bin = (unsigned)(key >> 40) & 0xFFFu;
                }
            }
            hist_add(h, bin, valid);
        }
        __syncthreads();
        h0 = h[4*tid]; h1 = h[4*tid+1]; h2 = h[4*tid+2]; h3 = h[4*tid+3];
        chunk = h0 + h1 + h2 + h3;
        S = suffix_scan(chunk, wtot, tid);
        {
            unsigned s4 = S - chunk;
            unsigned s3 = h3 + s4, s2 = h2 + s3, s1 = h1 + s2, s0 = h0 + s1;
            unsigned sf[5] = {s0, s1, s2, s3, s4};
            #pragma unroll
            for (int i = 0; i < 4; ++i)
                if (sf[i] >= rem && sf[i+1] < rem)
                    sT = (B1 << 52) | ((unsigned long long)(4*tid + i) << 40);
        }
        __syncthreads();

        // ---- Phase B: compact survivors, rank in smem ----
        const unsigned long long T = sT;
        for (int i = tid; i < n; i += 1024) {
            unsigned long long key = base[i];
            if (key >= T) {
                int p = atomicAdd(&scnt, 1);
                if (p < SURVCAP) sk[p] = key;
            }
        }
        __syncthreads();
        int m = scnt;

        if (m <= SURVCAP) {
            for (int i = tid; i < m; i += 1024) {
                unsigned long long key = sk[i];
                int r = 0;
                for (int j = 0; j < m; ++j) r += (sk[j] > key) ? 1 : 0;
                if (r < NKPT)
                    g_sel[b*NKPT + r] = HW - 1 - (int)(key & 0xffffffffu);
            }
        } else {
            // cold: exact rank via global scans, warp per survivor
            int lane = tid & 31, w = tid >> 5;
            for (int i = w; i < n; i += 32) {
                unsigned long long key = base[i];
                if (key < T) continue;
                int r = 0;
                for (int j = lane; j < n; j += 32)
                    r += (base[j] > key) ? 1 : 0;
                #pragma unroll
                for (int off = 16; off; off >>= 1)
                    r += __shfl_down_sync(0xffffffffu, r, off);
                if (lane == 0 && r < NKPT)
                    g_sel[b*NKPT + r] = HW - 1 - (int)(key & 0xffffffffu);
            }
        }
    }

    // cold: fewer than NKPT candidates -> ascending non-candidate indices
    if (n < NKPT) {
        __syncthreads();
        if (tid == 0) {
            int slot = n;
            for (int p = 0; p < HW && slot < NKPT; ++p)
                if (!g_cmask[b*HW + p]) g_sel[b*NKPT + (slot++)] = p;
        }
    }
}

// ---------------------------------------------------------------------------
// Gather: each thread handles 8 channels of one keypoint; kpts/pixels from
// groups 0..BB-1; resets g_count for next replay (strictly after k_select).
// ---------------------------------------------------------------------------
__global__ __launch_bounds__(256)
void k_gather(const float* __restrict__ bev,
              const float* __restrict__ feat,
              float* __restrict__ out) {
    int t = blockIdx.x * blockDim.x + threadIdx.x;   // 32768 threads
    if (t < BB) g_count[t] = 0;
    int k   = t & (NKPT-1);
    int grp = t >> 9;            // (b, cq): 4 * 16
    int b   = grp >> 4;
    int cq  = grp & 15;
    int idx = g_sel[b*NKPT + k];

    if (grp < BB) {
        int bk = grp;
        int idk = g_sel[bk*NKPT + k];
        int u = idk / WW, v = idk - u*WW;
        float4 kv = make_float4(bev[(bk*7 + 3)*HW + idk],
                                bev[(bk*7 + 4)*HW + idk], 0.f, 1.f);
        ((float4*)(out + OFF_KPTS))[bk*NKPT + k] = kv;
        ((float2*)(out + OFF_PIX))[bk*NKPT + k] =
            make_float2((float)u, (float)v);
    }

    const float* fb = feat + ((size_t)(b*NFEAT + cq*8))*HW + idx;
    float v0 = fb[0*HW];
    float v1 = fb[1*HW];
    float v2 = fb[2*HW];
    float v3 = fb[3*HW];
    float v4 = fb[4*HW];
    float v5 = fb[5*HW];
    float v6 = fb[6*HW];
    float v7 = fb[7*HW];
    float* ob = out + OFF_FEAS + (size_t)(b*NFEAT + cq*8)*NKPT + k;
    ob[0*NKPT] = v0;
    ob[1*NKPT] = v1;
    ob[2*NKPT] = v2;
    ob[3*NKPT] = v3;
    ob[4*NKPT] = v4;
    ob[5*NKPT] = v5;
    ob[6*NKPT] = v6;
    ob[7*NKPT] = v7;
}

extern "C" void kernel_launch(void* const* d_in, const int* in_sizes, int n_in,
                              void* d_out, int out_size) {
    const float* bev  = (const float*)d_in[0];
    const float* raw  = (const float*)d_in[1];
    const float* feat = (const float*)d_in[2];
    float* out = (float*)d_out;

    static bool attr_set = false;
    if (!attr_set) {
        cudaFuncSetAttribute(k_nms, cudaFuncAttributeMaxDynamicSharedMemorySize,
                             NMS_SMEM);
        attr_set = true;
    }

    dim3 ngrid(WW/TILE, HH/TILE, BB);   // 8 x 8 x 4
    k_nms<<<ngrid, NMS_THREADS, NMS_SMEM>>>(bev, raw, out);
    k_select<<<BB, 1024>>>();
    k_gather<<<128, 256>>>(bev, feat, out);
}

// round 15
// speedup vs baseline: 1.5356x; 1.0831x over previous
#include <cuda_runtime.h>
#include <math_constants.h>

#define BB 4
#define HH 512
#define WW 512
#define HW (HH*WW)
#define NKPT 512
#define CAP 65536
#define NFEAT 128

#define TILE 64
#define HALO 15
#define LDIM (TILE + 2*HALO)     // 94
#define GR 3                     // guard rows (top/bottom)
#define GC 4                     // guard cols left (16B alignment)
#define RROWS (LDIM + 2*GR)      // 100
#define SPITCH 104
#define BUF (RROWS*SPITCH)       // 10400
#define WPR 5                    // bit-words per row (slots 0,4 = zero guards)
#define NMS_SMEM (BUF*4*2 + RROWS*WPR*4*2)
#define NMS_THREADS 1024
#define NMS_NW (NMS_THREADS/32)

#define SURVCAP 3072

// Output layout (float32, reference tuple order)
#define OFF_SCORE 0
#define OFF_KPTS  (BB*HW)
#define OFF_FEAS  (OFF_KPTS + BB*NKPT*4)
#define OFF_PIX   (OFF_FEAS + BB*NFEAT*NKPT)

// Scratch
__device__ unsigned long long g_cand[BB*CAP];
__device__ unsigned char g_cmask[BB*HW];
__device__ int g_count[BB];
__device__ int g_sel[BB*NKPT];

// 4-row rolling vertical 7-max from a 10-row register window.
// r[0..9] = rows r0-3 .. r0+6; out[j] = max(rows r0+j-3 .. r0+j+3).
__device__ __forceinline__ void vmax4(const float* __restrict__ colp,
                                      float out[4]) {
    float r[10];
    #pragma unroll
    for (int i = 0; i < 10; ++i) r[i] = colp[(i-3)*SPITCH];
    float t[9];
    #pragma unroll
    for (int i = 0; i < 9; ++i) t[i] = fmaxf(r[i], r[i+1]);
    float q[7];
    #pragma unroll
    for (int i = 0; i < 7; ++i) q[i] = fmaxf(t[i], t[i+2]);
    #pragma unroll
    for (int j = 0; j < 4; ++j) out[j] = fmaxf(q[j], q[j+3]);
}

// Fused 7x7 OR-dilation of mk bits -> sup bits
template<int R0, int NR>
__device__ __forceinline__ void p34(const unsigned int* __restrict__ mkw,
                                    unsigned int* __restrict__ spw, int tid) {
    for (int t = tid; t < NR*3; t += NMS_THREADS) {
        int row = R0 + t / 3, w = t % 3 + 1;
        unsigned a = 0, c = 0, d = 0;
        #pragma unroll
        for (int k = -3; k <= 3; ++k) {
            const unsigned int* mr = mkw + (row+k)*WPR;
            a |= mr[w-1]; c |= mr[w]; d |= mr[w+1];
        }
        unsigned res = c;
        res |= __funnelshift_l(a, c, 1) | __funnelshift_r(c, d, 1);
        res |= __funnelshift_l(a, c, 2) | __funnelshift_r(c, d, 2);
        res |= __funnelshift_l(a, c, 3) | __funnelshift_r(c, d, 3);
        spw[row*WPR + w] = res;
    }
}

// quad h-pool of suppressed scores
template<int R0, int NR, int Q0, int NQt>
__device__ __forceinline__ void p5_quads(const float* __restrict__ sc,
                                         float* __restrict__ tp,
                                         const unsigned int* __restrict__ spw,
                                         int tid) {
    for (int t = tid; t < NR*NQt; t += NMS_THREADS) {
        int ly = R0 + t / NQt;
        int x  = (Q0 + t % NQt) << 2;
        const float* row = sc + ly*SPITCH;
        const unsigned int* srG = spw + (ly+GR)*WPR;  // word0 = bits -32..-1
        int Bp = x + 29;                              // (x-3) + 32
        unsigned w0 = srG[Bp >> 5];
        unsigned w1 = srG[(Bp >> 5) + 1];
        unsigned win = __funnelshift_r(w0, w1, Bp);
        float4 a = *(const float4*)(row + x - 4);
        float4 c = *(const float4*)(row + x);
        float4 e = *(const float4*)(row + x + 4);
        float s0 = (win & 1u)    ? 0.f : a.y;
        float s1 = (win & 2u)    ? 0.f : a.z;
        float s2 = (win & 4u)    ? 0.f : a.w;
        float s3 = (win & 8u)    ? 0.f : c.x;
        float s4 = (win & 16u)   ? 0.f : c.y;
        float s5 = (win & 32u)   ? 0.f : c.z;
        float s6 = (win & 64u)   ? 0.f : c.w;
        float s7 = (win & 128u)  ? 0.f : e.x;
        float s8 = (win & 256u)  ? 0.f : e.y;
        float s9 = (win & 512u)  ? 0.f : e.z;
        float mc = fmaxf(fmaxf(s3, s4), fmaxf(s5, s6));
        float m0 = fmaxf(fmaxf(mc, s0), fmaxf(s1, s2));
        float m1 = fmaxf(fmaxf(mc, s7), fmaxf(s1, s2));
        float m2 = fmaxf(fmaxf(mc, s2), fmaxf(s7, s8));
        float m3 = fmaxf(fmaxf(mc, s7), fmaxf(s8, s9));
        *(float4*)(tp + ly*SPITCH + x) = make_float4(m0, m1, m2, m3);
    }
}

// ---------------------------------------------------------------------------
// Fused NMS. One block per 64x64 tile, 1024 threads, 2 blocks/SM.
// Vertical passes use 4-row strip rolling windows (10 LDS per 4 rows).
// ---------------------------------------------------------------------------
__global__ __launch_bounds__(NMS_THREADS, 2)
void k_nms(const float* __restrict__ bev,
           const float* __restrict__ raw,
           float* __restrict__ out) {
    extern __shared__ unsigned char smraw[];
    float* sbuf = (float*)smraw;
    float* tbuf = sbuf + BUF;
    unsigned int* mkw = (unsigned int*)(tbuf + BUF);  // max_mask bits
    unsigned int* spw = mkw + RROWS*WPR;              // supp (7x7 dil) bits
    float* sc = sbuf + GR*SPITCH + GC;
    float* tp = tbuf + GR*SPITCH + GC;

    const int tid  = threadIdx.x;
    const int wid  = tid >> 5;
    const int lane = tid & 31;
    const int b    = blockIdx.z;
    const int gx0  = blockIdx.x * TILE - HALO;
    const int gy0  = blockIdx.y * TILE - HALO;
    const float* g2 = bev + (b*7 + 2)*HW;
    const float* rw = raw + b*HW;

    // bit arrays init (guard words/rows stay zero forever)
    for (int i = tid; i < RROWS*WPR; i += NMS_THREADS) {
        mkw[i] = 0; spw[i] = 0;
    }

    // fused init+load over the FULL ring: gated score or -inf
    for (int r = wid; r < RROWS; r += NMS_NW) {
        int gy = gy0 + (r - GR);
        const float* rwr = rw + gy*WW;
        const float* g2r = g2 + gy*WW;
        bool rowin = (unsigned)gy < HH;
        for (int col = lane; col < SPITCH; col += 32) {
            int gx = gx0 + (col - GC);
            float v = -CUDART_INF_F;
            if (rowin && (unsigned)gx < WW)
                v = rwr[gx] * (g2r[gx] > 0.f ? 1.f : 0.f);
            sbuf[r*SPITCH + col] = v;
        }
    }
    __syncthreads();

    // P1: h 7-max sc -> tp, quads, all 94 rows
    for (int t = tid; t < 94*24; t += NMS_THREADS) {
        int ly = t / 24;
        int x  = (t % 24) << 2;
        const float* row = sc + ly*SPITCH;
        float4 a = *(const float4*)(row + x - 4);
        float4 c = *(const float4*)(row + x);
        float4 e = *(const float4*)(row + x + 4);
        float mc = fmaxf(fmaxf(c.x, c.y), fmaxf(c.z, c.w));
        float m0 = fmaxf(fmaxf(mc, a.y), fmaxf(a.z, a.w));
        float m1 = fmaxf(fmaxf(mc, e.x), fmaxf(a.z, a.w));
        float m2 = fmaxf(fmaxf(mc, a.w), fmaxf(e.x, e.y));
        float m3 = fmaxf(fmaxf(mc, e.x), fmaxf(e.y, e.z));
        *(float4*)(tp + ly*SPITCH + x) = make_float4(m0, m1, m2, m3);
    }
    __syncthreads();
    // P2: v 7-max of tp over rows [3,91) in 4-row strips (22 strips x 3 grps);
    // mk bit = (max == sc) & in-image.
    for (int t = wid; t < 66; t += NMS_NW) {
        int s = t / 3, g = t % 3;
        int r0 = 3 + s*4;
        int lx = g*32 + lane;
        bool inb = lx < LDIM;
        float vm[4];
        vmax4(tp + r0*SPITCH + lx, vm);
        #pragma unroll
        for (int j = 0; j < 4; ++j) {
            bool pred = false;
            if (inb) {
                float sv = sc[(r0+j)*SPITCH + lx];
                pred = (vm[j] == sv && sv >= 0.f);
            }
            unsigned bal = __ballot_sync(0xffffffffu, pred);
            if (lane == 0) mkw[(r0+j+GR)*WPR + 1 + g] = bal;
        }
    }
    __syncthreads();

    // ---- iteration 0 ----
    p34<9, 82>(mkw, spw, tid);
    __syncthreads();
    p5_quads<6, 82, 0, 24>(sc, tp, spw, tid);
    __syncthreads();
    // P6 it0: rows [9,85) in 4-row strips (19 strips x 3 groups)
    for (int t = wid; t < 57; t += NMS_NW) {
        int s = t / 3, g = t % 3;
        int r0 = 9 + s*4;
        int lx = g*32 + lane;
        bool inb = lx < LDIM;
        float vm[4];
        vmax4(tp + r0*SPITCH + lx, vm);
        #pragma unroll
        for (int j = 0; j < 4; ++j) {
            bool cond = false;
            if (inb) {
                float sv = sc[(r0+j)*SPITCH + lx];
                unsigned supb = (spw[(r0+j+GR)*WPR + 1 + g] >> lane) & 1u;
                cond = (!supb && sv >= 0.f && vm[j] == sv);
            }
            unsigned bal = __ballot_sync(0xffffffffu, cond);
            if (lane == 0 && bal) mkw[(r0+j+GR)*WPR + 1 + g] |= bal;
        }
    }
    __syncthreads();

    // ---- iteration 1 ----
    p34<15, 70>(mkw, spw, tid);
    __syncthreads();
    p5_quads<12, 70, 3, 18>(sc, tp, spw, tid);
    __syncthreads();
    // P6 it1 (emit): interior only. 16 strips x 2 groups = 32 warp tasks.
    // ONE aggregated atomic per warp (4 rows).
    {
        int s = wid >> 1, g = wid & 1;
        int r0 = HALO + s*4;
        int lx = HALO + g*32 + lane;
        float vm[4];
        vmax4(tp + r0*SPITCH + lx, vm);
        unsigned cb[4];
        float svv[4];
        #pragma unroll
        for (int j = 0; j < 4; ++j) {
            int ly = r0 + j;
            float sv = sc[ly*SPITCH + lx];
            unsigned supb = (spw[(ly+GR)*WPR + 1 + (lx >> 5)]
                             >> (lx & 31)) & 1u;
            bool cond = (!supb && sv >= 0.f && vm[j] == sv);
            bool fm = cond || ((mkw[(ly+GR)*WPR + 1 + (lx >> 5)]
                                >> (lx & 31)) & 1u);
            int gg = (blockIdx.y*TILE + ly - HALO)*WW
                     + blockIdx.x*TILE + lx - HALO;
            out[OFF_SCORE + b*HW + gg] = sv;
            bool c = fm && (sv > 0.f);
            g_cmask[b*HW + gg] = c ? 1 : 0;
            cb[j] = __ballot_sync(0xffffffffu, c);
            svv[j] = sv;
        }
        int total = __popc(cb[0]) + __popc(cb[1])
                  + __popc(cb[2]) + __popc(cb[3]);
        int basep = 0;
        if (lane == 0 && total) basep = atomicAdd(&g_count[b], total);
        basep = __shfl_sync(0xffffffffu, basep, 0);
        #pragma unroll
        for (int j = 0; j < 4; ++j) {
            if ((cb[j] >> lane) & 1u) {
                int pos = basep + __popc(cb[j] & ((1u << lane) - 1u));
                if (pos < CAP) {
                    int gg = (blockIdx.y*TILE + r0 + j - HALO)*WW
                             + blockIdx.x*TILE + lx - HALO;
                    unsigned long long key =
                        ((unsigned long long)__float_as_uint(svv[j]) << 32)
                        | (unsigned int)(HW - 1 - gg);
                    g_cand[b*CAP + pos] = key;
                }
            }
            basep += __popc(cb[j]);
        }
    }
}

// warp-aggregated histogram add (convergence-safe)
__device__ __forceinline__ void hist_add(unsigned int* h, unsigned bin,
                                         bool valid) {
    unsigned vm = __ballot_sync(0xffffffffu, valid);
    if (valid) {
        unsigned peers = __match_any_sync(vm, bin);
        int lane = threadIdx.x & 31;
        if (lane == __ffs(peers) - 1)
            atomicAdd(&h[bin], (unsigned)__popc(peers));
    }
}

// Inclusive suffix scan (chunk granularity) across 1024 threads; 2 barriers.
__device__ __forceinline__ unsigned suffix_scan(unsigned chunk,
                                                unsigned* wtot, int tid) {
    int lane = tid & 31, wd = tid >> 5;
    unsigned v = chunk;
    #pragma unroll
    for (int off = 1; off < 32; off <<= 1) {
        unsigned o = __shfl_down_sync(0xffffffffu, v, off);
        if (lane + off < 32) v += o;
    }
    if (lane == 0) wtot[wd] = v;
    __syncthreads();
    if (wd == 0) {
        unsigned t = wtot[lane];
        unsigned s = t;
        #pragma unroll
        for (int off = 1; off < 32; off <<= 1) {
            unsigned o = __shfl_down_sync(0xffffffffu, s, off);
            if (lane + off < 32) s += o;
        }
        wtot[lane] = s - t;
    }
    __syncthreads();
    return v + wtot[wd];
}

// ---------------------------------------------------------------------------
// Merged threshold + select. One block per batch. NO writes to g_count here.
// ---------------------------------------------------------------------------
__global__ __launch_bounds__(1024)
void k_select() {
    __shared__ unsigned int h[4096];
    __shared__ unsigned int wtot[32];
    __shared__ unsigned long long sk[SURVCAP];
    __shared__ int sBin;
    __shared__ unsigned int sAbove;
    __shared__ unsigned long long sT;
    __shared__ int scnt;
    __shared__ int sn;

    const int b = blockIdx.x;
    const int tid = threadIdx.x;
    if (tid == 0) {
        sn = min(g_count[b], CAP);
        scnt = 0;
        sT = 0ULL;
    }
    __syncthreads();
    const int n = sn;
    const unsigned int target = (unsigned int)min(n, NKPT);
    const unsigned long long* base = g_cand + (size_t)b*CAP;

    if (target > 0) {
        const int nR = (n + 1023) & ~1023;

        // ---- level 1: bins = key bits [63:52] ----
        for (int i = tid; i < 4096; i += 1024) h[i] = 0;
        __syncthreads();
        for (int i = tid; i < nR; i += 1024) {
            bool valid = i < n;
            unsigned bin = valid ? (unsigned)(base[i] >> 52) : 0u;
            hist_add(h, bin, valid);
        }
        __syncthreads();
        unsigned h0 = h[4*tid], h1 = h[4*tid+1],
                 h2 = h[4*tid+2], h3 = h[4*tid+3];
        unsigned chunk = h0 + h1 + h2 + h3;
        unsigned S = suffix_scan(chunk, wtot, tid);
        {
            unsigned s4 = S - chunk;
            unsigned s3 = h3 + s4, s2 = h2 + s3, s1 = h1 + s2, s0 = h0 + s1;
            unsigned sf[5] = {s0, s1, s2, s3, s4};
            #pragma unroll
            for (int i = 0; i < 4; ++i)
                if (sf[i] >= target && sf[i+1] < target) {
                    sBin = 4*tid + i; sAbove = sf[i+1];
                }
        }
        __syncthreads();
        const unsigned long long B1 = (unsigned long long)sBin;
        const unsigned int rem = target - sAbove;   // >= 1

        // ---- level 2: bins = key bits [51:40], restricted to level-1 bin ----
        for (int i = tid; i < 4096; i += 1024) h[i] = 0;
        __syncthreads();
        for (int i = tid; i < nR; i += 1024) {
            bool valid = false;
            unsigned bin = 0;
            if (i < n) {
                unsigned long long key = base[i];
                if ((key >> 52) == B1) {
                    valid = true;
                    bin = (unsigned)(key >> 40) & 0xFFFu;
                }
            }
            hist_add(h, bin, valid);
        }
        __syncthreads();
        h0 = h[4*tid]; h1 = h[4*tid+1]; h2 = h[4*tid+2]; h3 = h[4*tid+3];
        chunk = h0 + h1 + h2 + h3;
        S = suffix_scan(chunk, wtot, tid);
        {
            unsigned s4 = S - chunk;
            unsigned s3 = h3 + s4, s2 = h2 + s3, s1 = h1 + s2, s0 = h0 + s1;
            unsigned sf[5] = {s0, s1, s2, s3, s4};
            #pragma unroll
            for (int i = 0; i < 4; ++i)
                if (sf[i] >= rem && sf[i+1] < rem)
                    sT = (B1 << 52) | ((unsigned long long)(4*tid + i) << 40);
        }
        __syncthreads();

        // ---- Phase B: compact survivors, rank in smem ----
        const unsigned long long T = sT;
        for (int i = tid; i < n; i += 1024) {
            unsigned long long key = base[i];
            if (key >= T) {
                int p = atomicAdd(&scnt, 1);
                if (p < SURVCAP) sk[p] = key;
            }
        }
        __syncthreads();
        int m = scnt;

        if (m <= SURVCAP) {
            for (int i = tid; i < m; i += 1024) {
                unsigned long long key = sk[i];
                int r = 0;
                for (int j = 0; j < m; ++j) r += (sk[j] > key) ? 1 : 0;
                if (r < NKPT)
                    g_sel[b*NKPT + r] = HW - 1 - (int)(key & 0xffffffffu);
            }
        } else {
            // cold: exact rank via global scans, warp per survivor
            int lane = tid & 31, w = tid >> 5;
            for (int i = w; i < n; i += 32) {
                unsigned long long key = base[i];
                if (key < T) continue;
                int r = 0;
                for (int j = lane; j < n; j += 32)
                    r += (base[j] > key) ? 1 : 0;
                #pragma unroll
                for (int off = 16; off; off >>= 1)
                    r += __shfl_down_sync(0xffffffffu, r, off);
                if (lane == 0 && r < NKPT)
                    g_sel[b*NKPT + r] = HW - 1 - (int)(key & 0xffffffffu);
            }
        }
    }

    // cold: fewer than NKPT candidates -> ascending non-candidate indices
    if (n < NKPT) {
        __syncthreads();
        if (tid == 0) {
            int slot = n;
            for (int p = 0; p < HW && slot < NKPT; ++p)
                if (!g_cmask[b*HW + p]) g_sel[b*NKPT + (slot++)] = p;
        }
    }
}

// ---------------------------------------------------------------------------
// Gather: each thread handles 8 channels of one keypoint; kpts/pixels from
// groups 0..BB-1; resets g_count for next replay (strictly after k_select).
// ---------------------------------------------------------------------------
__global__ __launch_bounds__(256)
void k_gather(const float* __restrict__ bev,
              const float* __restrict__ feat,
              float* __restrict__ out) {
    int t = blockIdx.x * blockDim.x + threadIdx.x;   // 32768 threads
    if (t < BB) g_count[t] = 0;
    int k   = t & (NKPT-1);
    int grp = t >> 9;            // (b, cq): 4 * 16
    int b   = grp >> 4;
    int cq  = grp & 15;
    int idx = g_sel[b*NKPT + k];

    if (grp < BB) {
        int bk = grp;
        int idk = g_sel[bk*NKPT + k];
        int u = idk / WW, v = idk - u*WW;
        float4 kv = make_float4(bev[(bk*7 + 3)*HW + idk],
                                bev[(bk*7 + 4)*HW + idk], 0.f, 1.f);
        ((float4*)(out + OFF_KPTS))[bk*NKPT + k] = kv;
        ((float2*)(out + OFF_PIX))[bk*NKPT + k] =
            make_float2((float)u, (float)v);
    }

    const float* fb = feat + ((size_t)(b*NFEAT + cq*8))*HW + idx;
    float v0 = fb[0*HW];
    float v1 = fb[1*HW];
    float v2 = fb[2*HW];
    float v3 = fb[3*HW];
    float v4 = fb[4*HW];
    float v5 = fb[5*HW];
    float v6 = fb[6*HW];
    float v7 = fb[7*HW];
    float* ob = out + OFF_FEAS + (size_t)(b*NFEAT + cq*8)*NKPT + k;
    ob[0*NKPT] = v0;
    ob[1*NKPT] = v1;
    ob[2*NKPT] = v2;
    ob[3*NKPT] = v3;
    ob[4*NKPT] = v4;
    ob[5*NKPT] = v5;
    ob[6*NKPT] = v6;
    ob[7*NKPT] = v7;
}

extern "C" void kernel_launch(void* const* d_in, const int* in_sizes, int n_in,
                              void* d_out, int out_size) {
    const float* bev  = (const float*)d_in[0];
    const float* raw  = (const float*)d_in[1];
    const float* feat = (const float*)d_in[2];
    float* out = (float*)d_out;

    static bool attr_set = false;
    if (!attr_set) {
        cudaFuncSetAttribute(k_nms, cudaFuncAttributeMaxDynamicSharedMemorySize,
                             NMS_SMEM);
        attr_set = true;
    }

    dim3 ngrid(WW/TILE, HH/TILE, BB);   // 8 x 8 x 4
    k_nms<<<ngrid, NMS_THREADS, NMS_SMEM>>>(bev, raw, out);
    k_select<<<BB, 1024>>>();
    k_gather<<<128, 256>>>(bev, feat, out);
}

// round 16
// speedup vs baseline: 1.5367x; 1.0007x over previous
#include <cuda_runtime.h>
#include <math_constants.h>

#define BB 4
#define HH 512
#define WW 512
#define HW (HH*WW)
#define NKPT 512
#define CAP 65536
#define NFEAT 128

#define TILE 64
#define HALO 15
#define LDIM (TILE + 2*HALO)     // 94
#define GR 3                     // guard rows (top/bottom)
#define GC 4                     // guard cols left (16B alignment)
#define RROWS (LDIM + 2*GR)      // 100
#define SPITCH 104
#define BUF (RROWS*SPITCH)       // 10400
#define WPR 5                    // bit-words per row (slots 0,4 = zero guards)
#define NMS_SMEM (BUF*4*2 + RROWS*WPR*4*2)
#define NMS_THREADS 1024
#define NMS_NW (NMS_THREADS/32)

#define SURVCAP 3072

// Output layout (float32, reference tuple order)
#define OFF_SCORE 0
#define OFF_KPTS  (BB*HW)
#define OFF_FEAS  (OFF_KPTS + BB*NKPT*4)
#define OFF_PIX   (OFF_FEAS + BB*NFEAT*NKPT)

// Scratch
__device__ unsigned long long g_cand[BB*CAP];
__device__ unsigned char g_cmask[BB*HW];
__device__ int g_count[BB];
__device__ int g_sel[BB*NKPT];

// 4-row rolling vertical 7-max from a 10-row register window.
__device__ __forceinline__ void vmax4(const float* __restrict__ colp,
                                      float out[4]) {
    float r[10];
    #pragma unroll
    for (int i = 0; i < 10; ++i) r[i] = colp[(i-3)*SPITCH];
    float t[9];
    #pragma unroll
    for (int i = 0; i < 9; ++i) t[i] = fmaxf(r[i], r[i+1]);
    float q[7];
    #pragma unroll
    for (int i = 0; i < 7; ++i) q[i] = fmaxf(t[i], t[i+2]);
    #pragma unroll
    for (int j = 0; j < 4; ++j) out[j] = fmaxf(q[j], q[j+3]);
}

// Fused 7x7 OR-dilation of mk bits -> sup bits
template<int R0, int NR>
__device__ __forceinline__ void p34(const unsigned int* __restrict__ mkw,
                                    unsigned int* __restrict__ spw, int tid) {
    for (int t = tid; t < NR*3; t += NMS_THREADS) {
        int row = R0 + t / 3, w = t % 3 + 1;
        unsigned a = 0, c = 0, d = 0;
        #pragma unroll
        for (int k = -3; k <= 3; ++k) {
            const unsigned int* mr = mkw + (row+k)*WPR;
            a |= mr[w-1]; c |= mr[w]; d |= mr[w+1];
        }
        unsigned res = c;
        res |= __funnelshift_l(a, c, 1) | __funnelshift_r(c, d, 1);
        res |= __funnelshift_l(a, c, 2) | __funnelshift_r(c, d, 2);
        res |= __funnelshift_l(a, c, 3) | __funnelshift_r(c, d, 3);
        spw[row*WPR + w] = res;
    }
}

// quad h-pool of suppressed scores
template<int R0, int NR, int Q0, int NQt>
__device__ __forceinline__ void p5_quads(const float* __restrict__ sc,
                                         float* __restrict__ tp,
                                         const unsigned int* __restrict__ spw,
                                         int tid) {
    for (int t = tid; t < NR*NQt; t += NMS_THREADS) {
        int ly = R0 + t / NQt;
        int x  = (Q0 + t % NQt) << 2;
        const float* row = sc + ly*SPITCH;
        const unsigned int* srG = spw + (ly+GR)*WPR;  // word0 = bits -32..-1
        int Bp = x + 29;                              // (x-3) + 32
        unsigned w0 = srG[Bp >> 5];
        unsigned w1 = srG[(Bp >> 5) + 1];
        unsigned win = __funnelshift_r(w0, w1, Bp);
        float4 a = *(const float4*)(row + x - 4);
        float4 c = *(const float4*)(row + x);
        float4 e = *(const float4*)(row + x + 4);
        float s0 = (win & 1u)    ? 0.f : a.y;
        float s1 = (win & 2u)    ? 0.f : a.z;
        float s2 = (win & 4u)    ? 0.f : a.w;
        float s3 = (win & 8u)    ? 0.f : c.x;
        float s4 = (win & 16u)   ? 0.f : c.y;
        float s5 = (win & 32u)   ? 0.f : c.z;
        float s6 = (win & 64u)   ? 0.f : c.w;
        float s7 = (win & 128u)  ? 0.f : e.x;
        float s8 = (win & 256u)  ? 0.f : e.y;
        float s9 = (win & 512u)  ? 0.f : e.z;
        float mc = fmaxf(fmaxf(s3, s4), fmaxf(s5, s6));
        float m0 = fmaxf(fmaxf(mc, s0), fmaxf(s1, s2));
        float m1 = fmaxf(fmaxf(mc, s7), fmaxf(s1, s2));
        float m2 = fmaxf(fmaxf(mc, s2), fmaxf(s7, s8));
        float m3 = fmaxf(fmaxf(mc, s7), fmaxf(s8, s9));
        *(float4*)(tp + ly*SPITCH + x) = make_float4(m0, m1, m2, m3);
    }
}

// ---------------------------------------------------------------------------
// Fused NMS. One block per 64x64 tile, 1024 threads, 2 blocks/SM.
// Load pass: float4 global loads (lanes 0-23 quads, lanes 24-31 edge cols).
// ---------------------------------------------------------------------------
__global__ __launch_bounds__(NMS_THREADS, 2)
void k_nms(const float* __restrict__ bev,
           const float* __restrict__ raw,
           float* __restrict__ out) {
    extern __shared__ unsigned char smraw[];
    float* sbuf = (float*)smraw;
    float* tbuf = sbuf + BUF;
    unsigned int* mkw = (unsigned int*)(tbuf + BUF);  // max_mask bits
    unsigned int* spw = mkw + RROWS*WPR;              // supp (7x7 dil) bits
    float* sc = sbuf + GR*SPITCH + GC;
    float* tp = tbuf + GR*SPITCH + GC;

    const int tid  = threadIdx.x;
    const int wid  = tid >> 5;
    const int lane = tid & 31;
    const int b    = blockIdx.z;
    const int gy0  = blockIdx.y * TILE - HALO;
    const int bx64 = blockIdx.x * TILE;
    const float* g2 = bev + (b*7 + 2)*HW;
    const float* rw = raw + b*HW;

    // bit arrays init (guard words/rows stay zero forever)
    for (int i = tid; i < RROWS*WPR; i += NMS_THREADS) {
        mkw[i] = 0; spw[i] = 0;
    }

    // load pass: warp per row; lanes 0-23 = aligned float4 quads (cols 3..98),
    // lanes 24-31 = edge columns {0,1,2,99..103}; -inf outside image.
    for (int r = wid; r < RROWS; r += NMS_NW) {
        int gy = gy0 + (r - GR);
        bool rowin = (unsigned)gy < HH;
        const float* rwr = rw + gy*WW;
        const float* g2r = g2 + gy*WW;
        if (lane < 24) {
            int col = 3 + (lane << 2);
            int gx = bx64 + col - 19;
            float4 v = make_float4(-CUDART_INF_F, -CUDART_INF_F,
                                   -CUDART_INF_F, -CUDART_INF_F);
            if (rowin) {
                if (gx >= 0 && gx + 3 < WW) {
                    float4 r4 = *(const float4*)(rwr + gx);
                    float4 g4 = *(const float4*)(g2r + gx);
                    v.x = r4.x * (g4.x > 0.f ? 1.f : 0.f);
                    v.y = r4.y * (g4.y > 0.f ? 1.f : 0.f);
                    v.z = r4.z * (g4.z > 0.f ? 1.f : 0.f);
                    v.w = r4.w * (g4.w > 0.f ? 1.f : 0.f);
                } else {
                    float* vp = &v.x;
                    #pragma unroll
                    for (int i = 0; i < 4; ++i) {
                        int gxi = gx + i;
                        if ((unsigned)gxi < WW)
                            vp[i] = rwr[gxi] * (g2r[gxi] > 0.f ? 1.f : 0.f);
                    }
                }
            }
            float* dst = sbuf + r*SPITCH + col;
            dst[0] = v.x; dst[1] = v.y; dst[2] = v.z; dst[3] = v.w;
        } else {
            int i8 = lane - 24;
            int col = (i8 < 3) ? i8 : 96 + i8;   // 0,1,2, 99..103
            int gx = bx64 + col - 19;
            float v = -CUDART_INF_F;
            if (rowin && (unsigned)gx < WW)
                v = rwr[gx] * (g2r[gx] > 0.f ? 1.f : 0.f);
            sbuf[r*SPITCH + col] = v;
        }
    }
    __syncthreads();

    // P1: h 7-max sc -> tp, quads, all 94 rows
    for (int t = tid; t < 94*24; t += NMS_THREADS) {
        int ly = t / 24;
        int x  = (t % 24) << 2;
        const float* row = sc + ly*SPITCH;
        float4 a = *(const float4*)(row + x - 4);
        float4 c = *(const float4*)(row + x);
        float4 e = *(const float4*)(row + x + 4);
        float mc = fmaxf(fmaxf(c.x, c.y), fmaxf(c.z, c.w));
        float m0 = fmaxf(fmaxf(mc, a.y), fmaxf(a.z, a.w));
        float m1 = fmaxf(fmaxf(mc, e.x), fmaxf(a.z, a.w));
        float m2 = fmaxf(fmaxf(mc, a.w), fmaxf(e.x, e.y));
        float m3 = fmaxf(fmaxf(mc, e.x), fmaxf(e.y, e.z));
        *(float4*)(tp + ly*SPITCH + x) = make_float4(m0, m1, m2, m3);
    }
    __syncthreads();
    // P2: v 7-max of tp over rows [3,91) in 4-row strips;
    // mk bit = (max == sc) & in-image.
    for (int t = wid; t < 66; t += NMS_NW) {
        int s = t / 3, g = t % 3;
        int r0 = 3 + s*4;
        int lx = g*32 + lane;
        bool inb = lx < LDIM;
        float vm[4];
        vmax4(tp + r0*SPITCH + lx, vm);
        #pragma unroll
        for (int j = 0; j < 4; ++j) {
            bool pred = false;
            if (inb) {
                float sv = sc[(r0+j)*SPITCH + lx];
                pred = (vm[j] == sv && sv >= 0.f);
            }
            unsigned bal = __ballot_sync(0xffffffffu, pred);
            if (lane == 0) mkw[(r0+j+GR)*WPR + 1 + g] = bal;
        }
    }
    __syncthreads();

    // ---- iteration 0 ----
    p34<9, 82>(mkw, spw, tid);
    __syncthreads();
    p5_quads<6, 82, 0, 24>(sc, tp, spw, tid);
    __syncthreads();
    // P6 it0: rows [9,85) in 4-row strips
    for (int t = wid; t < 57; t += NMS_NW) {
        int s = t / 3, g = t % 3;
        int r0 = 9 + s*4;
        int lx = g*32 + lane;
        bool inb = lx < LDIM;
        float vm[4];
        vmax4(tp + r0*SPITCH + lx, vm);
        #pragma unroll
        for (int j = 0; j < 4; ++j) {
            bool cond = false;
            if (inb) {
                float sv = sc[(r0+j)*SPITCH + lx];
                unsigned supb = (spw[(r0+j+GR)*WPR + 1 + g] >> lane) & 1u;
                cond = (!supb && sv >= 0.f && vm[j] == sv);
            }
            unsigned bal = __ballot_sync(0xffffffffu, cond);
            if (lane == 0 && bal) mkw[(r0+j+GR)*WPR + 1 + g] |= bal;
        }
    }
    __syncthreads();

    // ---- iteration 1 ----
    p34<15, 70>(mkw, spw, tid);
    __syncthreads();
    p5_quads<12, 70, 3, 18>(sc, tp, spw, tid);
    __syncthreads();
    // P6 it1 (emit): interior only; 16 strips x 2 groups = 32 warp tasks;
    // ONE aggregated atomic per warp (4 rows).
    {
        int s = wid >> 1, g = wid & 1;
        int r0 = HALO + s*4;
        int lx = HALO + g*32 + lane;
        float vm[4];
        vmax4(tp + r0*SPITCH + lx, vm);
        unsigned cb[4];
        float svv[4];
        #pragma unroll
        for (int j = 0; j < 4; ++j) {
            int ly = r0 + j;
            float sv = sc[ly*SPITCH + lx];
            unsigned supb = (spw[(ly+GR)*WPR + 1 + (lx >> 5)]
                             >> (lx & 31)) & 1u;
            bool cond = (!supb && sv >= 0.f && vm[j] == sv);
            bool fm = cond || ((mkw[(ly+GR)*WPR + 1 + (lx >> 5)]
                                >> (lx & 31)) & 1u);
            int gg = (blockIdx.y*TILE + ly - HALO)*WW
                     + bx64 + lx - HALO;
            out[OFF_SCORE + b*HW + gg] = sv;
            bool c = fm && (sv > 0.f);
            g_cmask[b*HW + gg] = c ? 1 : 0;
            cb[j] = __ballot_sync(0xffffffffu, c);
            svv[j] = sv;
        }
        int total = __popc(cb[0]) + __popc(cb[1])
                  + __popc(cb[2]) + __popc(cb[3]);
        int basep = 0;
        if (lane == 0 && total) basep = atomicAdd(&g_count[b], total);
        basep = __shfl_sync(0xffffffffu, basep, 0);
        #pragma unroll
        for (int j = 0; j < 4; ++j) {
            if ((cb[j] >> lane) & 1u) {
                int pos = basep + __popc(cb[j] & ((1u << lane) - 1u));
                if (pos < CAP) {
                    int gg = (blockIdx.y*TILE + r0 + j - HALO)*WW
                             + bx64 + lx - HALO;
                    unsigned long long key =
                        ((unsigned long long)__float_as_uint(svv[j]) << 32)
                        | (unsigned int)(HW - 1 - gg);
                    g_cand[b*CAP + pos] = key;
                }
            }
            basep += __popc(cb[j]);
        }
    }
}

// warp-aggregated histogram add (convergence-safe)
__device__ __forceinline__ void hist_add(unsigned int* h, unsigned bin,
                                         bool valid) {
    unsigned vm = __ballot_sync(0xffffffffu, valid);
    if (valid) {
        unsigned peers = __match_any_sync(vm, bin);
        int lane = threadIdx.x & 31;
        if (lane == __ffs(peers) - 1)
            atomicAdd(&h[bin], (unsigned)__popc(peers));
    }
}

// Inclusive suffix scan (chunk granularity) across 1024 threads; 2 barriers.
__device__ __forceinline__ unsigned suffix_scan(unsigned chunk,
                                                unsigned* wtot, int tid) {
    int lane = tid & 31, wd = tid >> 5;
    unsigned v = chunk;
    #pragma unroll
    for (int off = 1; off < 32; off <<= 1) {
        unsigned o = __shfl_down_sync(0xffffffffu, v, off);
        if (lane + off < 32) v += o;
    }
    if (lane == 0) wtot[wd] = v;
    __syncthreads();
    if (wd == 0) {
        unsigned t = wtot[lane];
        unsigned s = t;
        #pragma unroll
        for (int off = 1; off < 32; off <<= 1) {
            unsigned o = __shfl_down_sync(0xffffffffu, s, off);
            if (lane + off < 32) s += o;
        }
        wtot[lane] = s - t;
    }
    __syncthreads();
    return v + wtot[wd];
}

// ---------------------------------------------------------------------------
// Merged threshold + select. One block per batch. NO writes to g_count here.
// ---------------------------------------------------------------------------
__global__ __launch_bounds__(1024)
void k_select() {
    __shared__ unsigned int h[4096];
    __shared__ unsigned int wtot[32];
    __shared__ unsigned long long sk[SURVCAP];
    __shared__ int sBin;
    __shared__ unsigned int sAbove;
    __shared__ unsigned long long sT;
    __shared__ int scnt;
    __shared__ int sn;

    const int b = blockIdx.x;
    const int tid = threadIdx.x;
    if (tid == 0) {
        sn = min(g_count[b], CAP);
        scnt = 0;
        sT = 0ULL;
    }
    __syncthreads();
    const int n = sn;
    const unsigned int target = (unsigned int)min(n, NKPT);
    const unsigned long long* base = g_cand + (size_t)b*CAP;

    if (target > 0) {
        const int nR = (n + 1023) & ~1023;

        // ---- level 1: bins = key bits [63:52] ----
        for (int i = tid; i < 4096; i += 1024) h[i] = 0;
        __syncthreads();
        for (int i = tid; i < nR; i += 1024) {
            bool valid = i < n;
            unsigned bin = valid ? (unsigned)(base[i] >> 52) : 0u;
            hist_add(h, bin, valid);
        }
        __syncthreads();
        unsigned h0 = h[4*tid], h1 = h[4*tid+1],
                 h2 = h[4*tid+2], h3 = h[4*tid+3];
        unsigned chunk = h0 + h1 + h2 + h3;
        unsigned S = suffix_scan(chunk, wtot, tid);
        {
            unsigned s4 = S - chunk;
            unsigned s3 = h3 + s4, s2 = h2 + s3, s1 = h1 + s2, s0 = h0 + s1;
            unsigned sf[5] = {s0, s1, s2, s3, s4};
            #pragma unroll
            for (int i = 0; i < 4; ++i)
                if (sf[i] >= target && sf[i+1] < target) {
                    sBin = 4*tid + i; sAbove = sf[i+1];
                }
        }
        __syncthreads();
        const unsigned long long B1 = (unsigned long long)sBin;
        const unsigned int rem = target - sAbove;   // >= 1

        // ---- level 2: bins = key bits [51:40], restricted to level-1 bin ----
        for (int i = tid; i < 4096; i += 1024) h[i] = 0;
        __syncthreads();
        for (int i = tid; i < nR; i += 1024) {
            bool valid = false;
            unsigned bin = 0;
            if (i < n) {
                unsigned long long key = base[i];
                if ((key >> 52) == B1) {
                    valid = true;
                    bin = (unsigned)(key >> 40) & 0xFFFu;
                }
            }
            hist_add(h, bin, valid);
        }
        __syncthreads();
        h0 = h[4*tid]; h1 = h[4*tid+1]; h2 = h[4*tid+2]; h3 = h[4*tid+3];
        chunk = h0 + h1 + h2 + h3;
        S = suffix_scan(chunk, wtot, tid);
        {
            unsigned s4 = S - chunk;
            unsigned s3 = h3 + s4, s2 = h2 + s3, s1 = h1 + s2, s0 = h0 + s1;
            unsigned sf[5] = {s0, s1, s2, s3, s4};
            #pragma unroll
            for (int i = 0; i < 4; ++i)
                if (sf[i] >= rem && sf[i+1] < rem)
                    sT = (B1 << 52) | ((unsigned long long)(4*tid + i) << 40);
        }
        __syncthreads();

        // ---- Phase B: compact survivors, rank in smem ----
        const unsigned long long T = sT;
        for (int i = tid; i < n; i += 1024) {
            unsigned long long key = base[i];
            if (key >= T) {
                int p = atomicAdd(&scnt, 1);
                if (p < SURVCAP) sk[p] = key;
            }
        }
        __syncthreads();
        int m = scnt;

        if (m <= SURVCAP) {
            for (int i = tid; i < m; i += 1024) {
                unsigned long long key = sk[i];
                int r = 0;
                for (int j = 0; j < m; ++j) r += (sk[j] > key) ? 1 : 0;
                if (r < NKPT)
                    g_sel[b*NKPT + r] = HW - 1 - (int)(key & 0xffffffffu);
            }
        } else {
            // cold: exact rank via global scans, warp per survivor
            int lane = tid & 31, w = tid >> 5;
            for (int i = w; i < n; i += 32) {
                unsigned long long key = base[i];
                if (key < T) continue;
                int r = 0;
                for (int j = lane; j < n; j += 32)
                    r += (base[j] > key) ? 1 : 0;
                #pragma unroll
                for (int off = 16; off; off >>= 1)
                    r += __shfl_down_sync(0xffffffffu, r, off);
                if (lane == 0 && r < NKPT)
                    g_sel[b*NKPT + r] = HW - 1 - (int)(key & 0xffffffffu);
            }
        }
    }

    // cold: fewer than NKPT candidates -> ascending non-candidate indices
    if (n < NKPT) {
        __syncthreads();
        if (tid == 0) {
            int slot = n;
            for (int p = 0; p < HW && slot < NKPT; ++p)
                if (!g_cmask[b*HW + p]) g_sel[b*NKPT + (slot++)] = p;
        }
    }
}

// ---------------------------------------------------------------------------
// Gather: each thread handles 8 channels of one keypoint; kpts/pixels from
// groups 0..BB-1; resets g_count for next replay (strictly after k_select).
// ---------------------------------------------------------------------------
__global__ __launch_bounds__(256)
void k_gather(const float* __restrict__ bev,
              const float* __restrict__ feat,
              float* __restrict__ out) {
    int t = blockIdx.x * blockDim.x + threadIdx.x;   // 32768 threads
    if (t < BB) g_count[t] = 0;
    int k   = t & (NKPT-1);
    int grp = t >> 9;            // (b, cq): 4 * 16
    int b   = grp >> 4;
    int cq  = grp & 15;
    int idx = g_sel[b*NKPT + k];

    if (grp < BB) {
        int bk = grp;
        int idk = g_sel[bk*NKPT + k];
        int u = idk / WW, v = idk - u*WW;
        float4 kv = make_float4(bev[(bk*7 + 3)*HW + idk],
                                bev[(bk*7 + 4)*HW + idk], 0.f, 1.f);
        ((float4*)(out + OFF_KPTS))[bk*NKPT + k] = kv;
        ((float2*)(out + OFF_PIX))[bk*NKPT + k] =
            make_float2((float)u, (float)v);
    }

    const float* fb = feat + ((size_t)(b*NFEAT + cq*8))*HW + idx;
    float v0 = fb[0*HW];
    float v1 = fb[1*HW];
    float v2 = fb[2*HW];
    float v3 = fb[3*HW];
    float v4 = fb[4*HW];
    float v5 = fb[5*HW];
    float v6 = fb[6*HW];
    float v7 = fb[7*HW];
    float* ob = out + OFF_FEAS + (size_t)(b*NFEAT + cq*8)*NKPT + k;
    ob[0*NKPT] = v0;
    ob[1*NKPT] = v1;
    ob[2*NKPT] = v2;
    ob[3*NKPT] = v3;
    ob[4*NKPT] = v4;
    ob[5*NKPT] = v5;
    ob[6*NKPT] = v6;
    ob[7*NKPT] = v7;
}

extern "C" void kernel_launch(void* const* d_in, const int* in_sizes, int n_in,
                              void* d_out, int out_size) {
    const float* bev  = (const float*)d_in[0];
    const float* raw  = (const float*)d_in[1];
    const float* feat = (const float*)d_in[2];
    float* out = (float*)d_out;

    static bool attr_set = false;
    if (!attr_set) {
        cudaFuncSetAttribute(k_nms, cudaFuncAttributeMaxDynamicSharedMemorySize,
                             NMS_SMEM);
        attr_set = true;
    }

    dim3 ngrid(WW/TILE, HH/TILE, BB);   // 8 x 8 x 4
    k_nms<<<ngrid, NMS_THREADS, NMS_SMEM>>>(bev, raw, out);
    k_select<<<BB, 1024>>>();
    k_gather<<<128, 256>>>(bev, feat, out);
}